// round 2
// baseline (speedup 1.0000x reference)
#include <cuda_runtime.h>
#include <cstdint>

// Fixed problem shape
#define BATCH  65536
#define HID    4096
#define RDIM   256
#define EDIM   64
#define TOPK   2

// Scratch (device globals; no allocation allowed)
__device__ float g_P[(size_t)BATCH * RDIM];  // x @ Wp + bp   [B,256]
__device__ float g_T[(size_t)BATCH * RDIM];  // h@A + P@Bm    [B,256]

// ---------------------------------------------------------------------------
// Generic GEMM, N fixed at 256:  C[M,256] (+)= X[M,K] @ W[K,256] (+ bias)
// Block tile 64x256, BK=16, 256 threads, 8x8 microtile.
// ---------------------------------------------------------------------------
__global__ __launch_bounds__(256)
void gemm_n256(const float* __restrict__ X, const float* __restrict__ W,
               const float* __restrict__ bias, float* __restrict__ C,
               int M, int K, int accumulate)
{
    __shared__ float sX[64][16];
    __shared__ float sW[16][256];

    const int tid = threadIdx.x;
    const int tx  = tid & 31;      // column lane: cols tx + 32*j
    const int ty  = tid >> 5;      // 0..7      : rows ty + 8*i
    const int m0  = blockIdx.x * 64;

    const int xr = tid >> 2;       // 0..63  X-tile row
    const int xq = tid & 3;        // 0..3   X-tile k-quad
    const int wr = tid >> 6;       // 0..3   W-tile row base
    const int wc = tid & 63;       // 0..63  W-tile float4 col

    float acc[8][8];
#pragma unroll
    for (int i = 0; i < 8; i++)
#pragma unroll
        for (int j = 0; j < 8; j++) acc[i][j] = 0.f;

    for (int k0 = 0; k0 < K; k0 += 16) {
        // X tile [64 x 16]: one float4 per thread
        *reinterpret_cast<float4*>(&sX[xr][xq * 4]) =
            *reinterpret_cast<const float4*>(X + (size_t)(m0 + xr) * K + k0 + xq * 4);
        // W tile [16 x 256]: four float4 per thread
#pragma unroll
        for (int r = 0; r < 4; r++) {
            *reinterpret_cast<float4*>(&sW[wr + 4 * r][wc * 4]) =
                *reinterpret_cast<const float4*>(W + (size_t)(k0 + wr + 4 * r) * 256 + wc * 4);
        }
        __syncthreads();

#pragma unroll
        for (int k = 0; k < 16; k++) {
            float a[8], b[8];
#pragma unroll
            for (int i = 0; i < 8; i++) a[i] = sX[ty + 8 * i][k];    // broadcast
#pragma unroll
            for (int j = 0; j < 8; j++) b[j] = sW[k][tx + 32 * j];   // conflict-free
#pragma unroll
            for (int i = 0; i < 8; i++)
#pragma unroll
                for (int j = 0; j < 8; j++)
                    acc[i][j] = fmaf(a[i], b[j], acc[i][j]);
        }
        __syncthreads();
    }

#pragma unroll
    for (int i = 0; i < 8; i++) {
        size_t row = (size_t)(m0 + ty + 8 * i);
#pragma unroll
        for (int j = 0; j < 8; j++) {
            int col = tx + 32 * j;
            size_t idx = row * 256 + col;
            float v = acc[i][j];
            if (bias) v += bias[col];
            if (accumulate) v += C[idx];
            C[idx] = v;
        }
    }
}

// ---------------------------------------------------------------------------
// Epilogue per row:
//   h_new = h + 0.1*(-h/tau + tanh(T))
//   logits = h_new @ Wg + bg ; +0.1 at prev_sel ; top-2 ; softmax
// ---------------------------------------------------------------------------
__global__ __launch_bounds__(256)
void k_epilogue(const float* __restrict__ h,
                const int* __restrict__ prev_sel,
                const float* __restrict__ tau,
                const float* __restrict__ Wg,
                const float* __restrict__ bg,
                float* __restrict__ out, int B, int out_elems)
{
    int row = blockIdx.x;
    int j = threadIdx.x;

    __shared__ float s_hnew[RDIM];
    __shared__ float s_part[4][EDIM];
    __shared__ float s_logit[EDIM];

    float hj = h[(size_t)row * RDIM + j];
    float Tj = g_T[(size_t)row * RDIM + j];
    float hn = hj + 0.1f * (-hj / tau[j] + tanhf(Tj));
    s_hnew[j] = hn;
    __syncthreads();

    int e = j & 63;
    int p = j >> 6;
    float acc = 0.f;
#pragma unroll 8
    for (int k = p * 64; k < p * 64 + 64; k++)
        acc = fmaf(s_hnew[k], Wg[k * EDIM + e], acc);
    s_part[p][e] = acc;
    __syncthreads();

    if (j < EDIM) {
        float lg = s_part[0][j] + s_part[1][j] + s_part[2][j] + s_part[3][j] + bg[j];
        int p0 = prev_sel[(size_t)row * TOPK + 0];
        int p1 = prev_sel[(size_t)row * TOPK + 1];
        if (j == p0 || j == p1) lg += 0.1f;   // scatter .set(0.1) then add
        s_logit[j] = lg;
    }
    __syncthreads();

    if (j == 0) {
        float v1 = -1e30f, v2 = -1e30f;
        int i1 = 0, i2 = 0;
#pragma unroll
        for (int q = 0; q < EDIM; q++) {
            float v = s_logit[q];
            if (v > v1) { v2 = v1; i2 = i1; v1 = v; i1 = q; }
            else if (v > v2) { v2 = v; i2 = q; }
        }
        float e2 = expf(v2 - v1);
        float s  = 1.f + e2;
        float w1 = 1.f / s;
        float w2 = e2 / s;
        // layout: [top_idx flat (2B)] ++ [top_w flat (2B)]
        out[(size_t)row * 2 + 0] = (float)i1;
        out[(size_t)row * 2 + 1] = (float)i2;
        size_t woff = (size_t)out_elems / 2;   // = 2B when out_elems = 4B
        out[woff + (size_t)row * 2 + 0] = w1;
        out[woff + (size_t)row * 2 + 1] = w2;
    }
}

// ---------------------------------------------------------------------------
extern "C" void kernel_launch(void* const* d_in, const int* in_sizes, int n_in,
                              void* d_out, int out_size)
{
    // Resolve inputs by element count (robust to metadata reordering).
    // Pairs with equal sizes (bp/tau, A/Bm) keep first/second occurrence order,
    // which holds for both dict order and alphabetical order.
    const float *x = 0, *h = 0, *Wp = 0, *bp = 0, *tau = 0, *A = 0, *Bm = 0, *Wg = 0, *bg = 0;
    const int *prev_sel = 0;
    for (int i = 0; i < n_in; i++) {
        int s = in_sizes[i];
        const void* pv = d_in[i];
        switch (s) {
            case BATCH * HID:            x = (const float*)pv; break;          // 268435456
            case BATCH * RDIM:           h = (const float*)pv; break;          // 16777216
            case BATCH * TOPK:           prev_sel = (const int*)pv; break;     // 131072
            case HID * RDIM:             Wp = (const float*)pv; break;         // 1048576
            case RDIM:                   if (!bp) bp = (const float*)pv; else tau = (const float*)pv; break;
            case RDIM * RDIM:            if (!A)  A  = (const float*)pv; else Bm  = (const float*)pv; break;
            case RDIM * EDIM:            Wg = (const float*)pv; break;         // 16384
            case EDIM:                   bg = (const float*)pv; break;         // 64
            default: break;
        }
    }
    // Fallback to positional order if anything missing
    if (!x)        x        = (const float*)d_in[0];
    if (!h)        h        = (const float*)d_in[1];
    if (!prev_sel) prev_sel = (const int*)  d_in[2];
    if (!Wp)       Wp       = (const float*)d_in[3];
    if (!bp)       bp       = (const float*)d_in[4];
    if (!tau)      tau      = (const float*)d_in[5];
    if (!A)        A        = (const float*)d_in[6];
    if (!Bm)       Bm       = (const float*)d_in[7];
    if (!Wg)       Wg       = (const float*)d_in[8];
    if (!bg)       bg       = (const float*)d_in[9];

    float* out = (float*)d_out;
    const int B = BATCH;

    float *Pp = 0, *Tp = 0;
    cudaGetSymbolAddress((void**)&Pp, g_P);
    cudaGetSymbolAddress((void**)&Tp, g_T);

    // 1) P = x @ Wp + bp          (K = 4096)
    gemm_n256<<<B / 64, 256>>>(x, Wp, bp, Pp, B, HID, 0);
    // 2) T = h @ A                (K = 256)
    gemm_n256<<<B / 64, 256>>>(h, A, (const float*)0, Tp, B, RDIM, 0);
    // 3) T += P @ Bm              (K = 256)
    gemm_n256<<<B / 64, 256>>>(Pp, Bm, (const float*)0, Tp, B, RDIM, 1);
    // 4) epilogue
    k_epilogue<<<B, 256>>>(h, prev_sel, tau, Wg, bg, out, B, out_size);
}

// round 4
// speedup vs baseline: 1.3460x; 1.3460x over previous
#include <cuda_runtime.h>
#include <cstdint>

#define BATCH 65536
#define HID   4096
#define RDIM  256
#define EDIM  64
#define TOPK  2

// ---------------- device scratch ----------------
__device__ float g_P[(size_t)BATCH * RDIM];        // x@Wp + bp
__device__ float g_T[(size_t)BATCH * RDIM];        // h@A + P@Bm
__device__ float g_Wp_hi[(size_t)HID * RDIM];      // tf32 split of Wp, [K][N] k-major
__device__ float g_Wp_lo[(size_t)HID * RDIM];
__device__ float g_C_hi[(size_t)512 * RDIM];       // [A;Bm] stacked, [K][N]
__device__ float g_C_lo[(size_t)512 * RDIM];

// ---------------- helpers ----------------
__device__ __forceinline__ uint32_t smem_u32(const void* p) {
    uint32_t a;
    asm("{ .reg .u64 t; cvta.to.shared.u64 t, %1; cvt.u32.u64 %0, t; }"
        : "=r"(a) : "l"(p));
    return a;
}
__device__ __forceinline__ void split_tf32(float v, float& hi, float& lo) {
    uint32_t u;
    asm("cvt.rna.tf32.f32 %0, %1;" : "=r"(u) : "f"(v));
    hi = __uint_as_float(u);
    float r = v - hi;
    uint32_t u2;
    asm("cvt.rna.tf32.f32 %0, %1;" : "=r"(u2) : "f"(r));
    lo = __uint_as_float(u2);
}
__device__ __forceinline__ void mma_tf32(float d[4],
                                         uint32_t a0, uint32_t a1, uint32_t a2, uint32_t a3,
                                         uint32_t b0, uint32_t b1) {
    asm volatile(
        "mma.sync.aligned.m16n8k8.row.col.f32.tf32.tf32.f32 "
        "{%0,%1,%2,%3}, {%4,%5,%6,%7}, {%8,%9}, {%0,%1,%2,%3};"
        : "+f"(d[0]), "+f"(d[1]), "+f"(d[2]), "+f"(d[3])
        : "r"(a0), "r"(a1), "r"(a2), "r"(a3), "r"(b0), "r"(b1));
}
#define CP_ASYNC16(dst, src) \
    asm volatile("cp.async.cg.shared.global [%0], [%1], 16;" :: "r"(dst), "l"(src))
#define CP_COMMIT() asm volatile("cp.async.commit_group;" ::: "memory")
#define CP_WAIT0()  asm volatile("cp.async.wait_group 0;" ::: "memory")

// ---------------- SMEM layout (bytes) ----------------
// A tiles: [128 rows][36 floats] = 18432 B each; hi buf0,buf1 then lo buf0,buf1
// B tiles: [32 rows][260 floats] = 33280 B each; hi buf0,buf1 then lo buf0,buf1
#define A_STRIDE 36
#define B_STRIDE 260
#define OFF_AH(buf) ((buf) * 18432)
#define OFF_AL(buf) (36864 + (buf) * 18432)
#define OFF_BH(buf) (73728 + (buf) * 33280)
#define OFF_BL(buf) (140288 + (buf) * 33280)
#define SMEM_GEMM   206848

// ===========================================================================
// 3xTF32 GEMM via mma.sync: C[M,256] = X[M,Ktot] @ W[Ktot,256] (+ bias)
//   X = concat(X1 [first K1 cols, row stride K1], X2 [rest, row stride Ktot-K1])
//   Bh/Bl: tf32 hi/lo of W in original [K][256] layout.
// CTA 128x256, BK=32, 256 threads, warp tile 64x64.
// ===========================================================================
__global__ __launch_bounds__(256, 1)
void gemm3xtf32(const float* __restrict__ X1, int K1,
                const float* __restrict__ X2, int Ktot,
                const float* __restrict__ Bh, const float* __restrict__ Bl,
                const float* __restrict__ bias, float* __restrict__ C)
{
    extern __shared__ __align__(128) char smem[];
    const uint32_t sb = smem_u32(smem);

    const int tid  = threadIdx.x;
    const int warp = tid >> 5;
    const int lane = tid & 31;
    const int g    = lane >> 2;   // 0..7
    const int tg   = lane & 3;    // 0..3
    const int wm   = (warp >> 2) * 64;   // 0 / 64
    const int wn   = (warp & 3) * 64;    // 0 / 64 / 128 / 192
    const int m0   = blockIdx.x * 128;
    const int K2   = Ktot - K1;
    const int ns   = Ktot / 32;

    // A global-load mapping: 16 floats / thread / stage
    const int ar = tid >> 1;      // 0..127 row
    const int ah = tid & 1;       // 0..1 half (16 cols)

    float d[4][8][4];
#pragma unroll
    for (int mt = 0; mt < 4; mt++)
#pragma unroll
        for (int nt = 0; nt < 8; nt++)
#pragma unroll
            for (int q = 0; q < 4; q++) d[mt][nt][q] = 0.f;

    float4 apre[4];

    // ---- helpers as lambdas ----
    auto load_A_regs = [&](int k0) {
#pragma unroll
        for (int q = 0; q < 4; q++) {
            int kg = k0 + ah * 16 + q * 4;
            const float* src = (kg < K1)
                ? (X1 + (size_t)(m0 + ar) * K1 + kg)
                : (X2 + (size_t)(m0 + ar) * K2 + (kg - K1));
            apre[q] = *reinterpret_cast<const float4*>(src);
        }
    };
    auto store_A_smem = [&](int buf) {
        float* Ah = (float*)(smem + OFF_AH(buf));
        float* Al = (float*)(smem + OFF_AL(buf));
#pragma unroll
        for (int q = 0; q < 4; q++) {
            float4 hi, lo;
            split_tf32(apre[q].x, hi.x, lo.x);
            split_tf32(apre[q].y, hi.y, lo.y);
            split_tf32(apre[q].z, hi.z, lo.z);
            split_tf32(apre[q].w, hi.w, lo.w);
            int off = ar * A_STRIDE + ah * 16 + q * 4;
            *reinterpret_cast<float4*>(Ah + off) = hi;
            *reinterpret_cast<float4*>(Al + off) = lo;
        }
    };
    auto issue_B = [&](int k0, int buf) {
        uint32_t dh = sb + OFF_BH(buf);
        uint32_t dl = sb + OFF_BL(buf);
#pragma unroll
        for (int i = 0; i < 8; i++) {
            int linear = i * 256 + tid;      // 0..2047
            int krow = linear >> 6;          // 0..31
            int c16  = linear & 63;          // 0..63
            uint32_t doff = (uint32_t)(krow * (B_STRIDE * 4) + c16 * 16);
            const float* sh = Bh + (size_t)(k0 + krow) * 256 + c16 * 4;
            const float* sl = Bl + (size_t)(k0 + krow) * 256 + c16 * 4;
            CP_ASYNC16(dh + doff, sh);
            CP_ASYNC16(dl + doff, sl);
        }
        CP_COMMIT();
    };
    auto compute = [&](int buf) {
        const float* Ah = (const float*)(smem + OFF_AH(buf));
        const float* Al = (const float*)(smem + OFF_AL(buf));
        const float* Bh_s = (const float*)(smem + OFF_BH(buf));
        const float* Bl_s = (const float*)(smem + OFF_BL(buf));
#pragma unroll
        for (int k8 = 0; k8 < 4; k8++) {
            const int kk = k8 * 8;
            uint32_t fah[4][4], fal[4][4];
#pragma unroll
            for (int mt = 0; mt < 4; mt++) {
                int base = (wm + mt * 16 + g) * A_STRIDE + kk + tg;
                fah[mt][0] = __float_as_uint(Ah[base]);
                fah[mt][1] = __float_as_uint(Ah[base + 8 * A_STRIDE]);
                fah[mt][2] = __float_as_uint(Ah[base + 4]);
                fah[mt][3] = __float_as_uint(Ah[base + 8 * A_STRIDE + 4]);
                fal[mt][0] = __float_as_uint(Al[base]);
                fal[mt][1] = __float_as_uint(Al[base + 8 * A_STRIDE]);
                fal[mt][2] = __float_as_uint(Al[base + 4]);
                fal[mt][3] = __float_as_uint(Al[base + 8 * A_STRIDE + 4]);
            }
#pragma unroll
            for (int nt = 0; nt < 8; nt++) {
                int nb = wn + nt * 8 + g;
                uint32_t bh0 = __float_as_uint(Bh_s[(kk + tg) * B_STRIDE + nb]);
                uint32_t bh1 = __float_as_uint(Bh_s[(kk + tg + 4) * B_STRIDE + nb]);
                uint32_t bl0 = __float_as_uint(Bl_s[(kk + tg) * B_STRIDE + nb]);
                uint32_t bl1 = __float_as_uint(Bl_s[(kk + tg + 4) * B_STRIDE + nb]);
#pragma unroll
                for (int mt = 0; mt < 4; mt++) {
                    mma_tf32(d[mt][nt], fah[mt][0], fah[mt][1], fah[mt][2], fah[mt][3], bh0, bh1);
                    mma_tf32(d[mt][nt], fah[mt][0], fah[mt][1], fah[mt][2], fah[mt][3], bl0, bl1);
                    mma_tf32(d[mt][nt], fal[mt][0], fal[mt][1], fal[mt][2], fal[mt][3], bh0, bh1);
                }
            }
        }
    };

    // ---- prologue: stage 0 ----
    load_A_regs(0);
    issue_B(0, 0);
    store_A_smem(0);
    CP_WAIT0();
    __syncthreads();

    // ---- main loop ----
    for (int s = 0; s < ns; s++) {
        const int buf = s & 1;
        const int nbuf = buf ^ 1;
        const bool more = (s + 1 < ns);
        if (more) {
            load_A_regs((s + 1) * 32);
            issue_B((s + 1) * 32, nbuf);
        }
        compute(buf);
        if (more) store_A_smem(nbuf);
        CP_WAIT0();
        __syncthreads();
    }

    // ---- writeback ----
#pragma unroll
    for (int mt = 0; mt < 4; mt++) {
        int r0 = m0 + wm + mt * 16 + g;
#pragma unroll
        for (int nt = 0; nt < 8; nt++) {
            int c0 = wn + nt * 8 + tg * 2;
            float b0 = bias ? bias[c0] : 0.f;
            float b1 = bias ? bias[c0 + 1] : 0.f;
            float2 v01 = make_float2(d[mt][nt][0] + b0, d[mt][nt][1] + b1);
            float2 v23 = make_float2(d[mt][nt][2] + b0, d[mt][nt][3] + b1);
            *reinterpret_cast<float2*>(C + (size_t)r0 * 256 + c0) = v01;
            *reinterpret_cast<float2*>(C + (size_t)(r0 + 8) * 256 + c0) = v23;
        }
    }
}

// ===========================================================================
// Weight split kernels (no transpose; keep [K][256] layout)
// ===========================================================================
__global__ void k_split_wp(const float* __restrict__ Wp) {
    int k = blockIdx.x, n = threadIdx.x;
    float hi, lo;
    split_tf32(Wp[(size_t)k * RDIM + n], hi, lo);
    g_Wp_hi[(size_t)k * RDIM + n] = hi;
    g_Wp_lo[(size_t)k * RDIM + n] = lo;
}
__global__ void k_split_c(const float* __restrict__ A, const float* __restrict__ Bm) {
    int k = blockIdx.x, n = threadIdx.x;
    float v = (k < RDIM) ? A[(size_t)k * RDIM + n] : Bm[(size_t)(k - RDIM) * RDIM + n];
    float hi, lo;
    split_tf32(v, hi, lo);
    g_C_hi[(size_t)k * RDIM + n] = hi;
    g_C_lo[(size_t)k * RDIM + n] = lo;
}

// ===========================================================================
// Epilogue: 16 rows per block, Wg cached in SMEM.
// ===========================================================================
#define SMEM_EPI (65536 + 16384 + 4096)
__global__ __launch_bounds__(256)
void k_epilogue2(const float* __restrict__ h, const int* __restrict__ prev_sel,
                 const float* __restrict__ tau, const float* __restrict__ Wg,
                 const float* __restrict__ bg, float* __restrict__ out, int B)
{
    extern __shared__ __align__(16) char esm[];
    float* sWg = (float*)esm;              // [256*64]
    float* sH  = (float*)(esm + 65536);    // [16*256]
    float* sL  = (float*)(esm + 81920);    // [16*64]
    const int tid = threadIdx.x;
    const size_t r0 = (size_t)blockIdx.x * 16;

#pragma unroll
    for (int i = 0; i < 16; i++) {
        int f = i * 256 + tid;
        reinterpret_cast<float4*>(sWg)[f] = reinterpret_cast<const float4*>(Wg)[f];
    }
#pragma unroll
    for (int i = 0; i < 16; i++) {
        int idx = i * 256 + tid;
        int row = idx >> 8, col = idx & 255;
        size_t gidx = (r0 + row) * 256 + col;
        float hj = h[gidx];
        float Tj = g_T[gidx];
        sH[idx] = hj + 0.1f * (-hj / tau[col] + tanhf(Tj));
    }
    __syncthreads();

#pragma unroll
    for (int i = 0; i < 4; i++) {
        int c = i * 256 + tid;
        int row = c >> 6, e = c & 63;
        float acc = 0.f;
#pragma unroll 8
        for (int k = 0; k < 256; k++)
            acc = fmaf(sH[row * 256 + k], sWg[k * 64 + e], acc);
        sL[c] = acc + bg[e];
    }
    __syncthreads();

    if (tid < 16) {
        int row = tid;
        int p0 = prev_sel[(r0 + row) * 2 + 0];
        int p1 = prev_sel[(r0 + row) * 2 + 1];
        float v1 = -1e30f, v2 = -1e30f;
        int i1 = 0, i2 = 0;
#pragma unroll
        for (int q = 0; q < 64; q++) {
            float v = sL[row * 64 + q] + ((q == p0 || q == p1) ? 0.1f : 0.f);
            if (v > v1) { v2 = v1; i2 = i1; v1 = v; i1 = q; }
            else if (v > v2) { v2 = v; i2 = q; }
        }
        float e2 = expf(v2 - v1);
        float sm = 1.f + e2;
        size_t orow = r0 + row;
        out[orow * 2 + 0] = (float)i1;
        out[orow * 2 + 1] = (float)i2;
        size_t woff = (size_t)2 * B;
        out[woff + orow * 2 + 0] = 1.f / sm;
        out[woff + orow * 2 + 1] = e2 / sm;
    }
}

// ===========================================================================
extern "C" void kernel_launch(void* const* d_in, const int* in_sizes, int n_in,
                              void* d_out, int out_size)
{
    const float *x = 0, *h = 0, *Wp = 0, *bp = 0, *tau = 0, *A = 0, *Bm = 0,
                *Wg = 0, *bg = 0;
    const int* prev_sel = 0;
    for (int i = 0; i < n_in; i++) {
        int s = in_sizes[i];
        const void* pv = d_in[i];
        switch (s) {
            case BATCH * HID:  x = (const float*)pv; break;
            case BATCH * RDIM: h = (const float*)pv; break;
            case BATCH * TOPK: prev_sel = (const int*)pv; break;
            case HID * RDIM:   Wp = (const float*)pv; break;
            case RDIM:         if (!bp) bp = (const float*)pv; else tau = (const float*)pv; break;
            case RDIM * RDIM:  if (!A) A = (const float*)pv; else Bm = (const float*)pv; break;
            case RDIM * EDIM:  Wg = (const float*)pv; break;
            case EDIM:         bg = (const float*)pv; break;
            default: break;
        }
    }
    if (!x)        x        = (const float*)d_in[0];
    if (!h)        h        = (const float*)d_in[1];
    if (!prev_sel) prev_sel = (const int*)d_in[2];
    if (!Wp)       Wp       = (const float*)d_in[3];
    if (!bp)       bp       = (const float*)d_in[4];
    if (!tau)      tau      = (const float*)d_in[5];
    if (!A)        A        = (const float*)d_in[6];
    if (!Bm)       Bm       = (const float*)d_in[7];
    if (!Wg)       Wg       = (const float*)d_in[8];
    if (!bg)       bg       = (const float*)d_in[9];

    static int attr_done = 0;
    if (!attr_done) {
        cudaFuncSetAttribute(gemm3xtf32, cudaFuncAttributeMaxDynamicSharedMemorySize, SMEM_GEMM);
        cudaFuncSetAttribute(k_epilogue2, cudaFuncAttributeMaxDynamicSharedMemorySize, SMEM_EPI);
        attr_done = 1;
    }

    float *Pp = 0, *Tp = 0, *Wph = 0, *Wpl = 0, *Ch = 0, *Cl = 0;
    cudaGetSymbolAddress((void**)&Pp, g_P);
    cudaGetSymbolAddress((void**)&Tp, g_T);
    cudaGetSymbolAddress((void**)&Wph, g_Wp_hi);
    cudaGetSymbolAddress((void**)&Wpl, g_Wp_lo);
    cudaGetSymbolAddress((void**)&Ch, g_C_hi);
    cudaGetSymbolAddress((void**)&Cl, g_C_lo);

    float* out = (float*)d_out;

    // weight prep (tf32 splits)
    k_split_wp<<<HID, 256>>>(Wp);
    k_split_c<<<512, 256>>>(A, Bm);
    // P = x @ Wp + bp          (3xTF32, K=4096)
    gemm3xtf32<<<BATCH / 128, 256, SMEM_GEMM>>>(x, HID, x, HID, Wph, Wpl, bp, Pp);
    // T = [h | P] @ [A; Bm]    (3xTF32, K=512)
    gemm3xtf32<<<BATCH / 128, 256, SMEM_GEMM>>>(h, RDIM, Pp, 512, Ch, Cl,
                                                (const float*)0, Tp);
    // epilogue
    k_epilogue2<<<BATCH / 16, 256, SMEM_EPI>>>(h, prev_sel, tau, Wg, bg, out, BATCH);
}

// round 5
// speedup vs baseline: 1.4705x; 1.0925x over previous
#include <cuda_runtime.h>
#include <cstdint>

#define BATCH 65536
#define HID   4096
#define RDIM  256
#define EDIM  64
#define TOPK  2
#define KTOT  (RDIM + HID)        // 4352
#define NS    (KTOT / 32)         // 136 stages

// ---------------- device scratch ----------------
__device__ float g_W[(size_t)KTOT * RDIM];   // [A ; Wp@Bm] stacked, [K][256]
__device__ float g_c[RDIM];                  // bp @ Bm
__device__ float g_T[(size_t)BATCH * RDIM];  // h@A + x@Wf

// ---------------- helpers ----------------
__device__ __forceinline__ uint32_t smem_u32(const void* p) {
    uint32_t a;
    asm("{ .reg .u64 t; cvta.to.shared.u64 t, %1; cvt.u32.u64 %0, t; }"
        : "=r"(a) : "l"(p));
    return a;
}
__device__ __forceinline__ void split_tf32(float v, uint32_t& hi, uint32_t& lo) {
    uint32_t u;
    asm("cvt.rna.tf32.f32 %0, %1;" : "=r"(u) : "f"(v));
    hi = u;
    float r = v - __uint_as_float(u);
    asm("cvt.rna.tf32.f32 %0, %1;" : "=r"(lo) : "f"(r));
}
__device__ __forceinline__ void mma_tf32(float d[4],
                                         const uint32_t a[4],
                                         uint32_t b0, uint32_t b1) {
    asm volatile(
        "mma.sync.aligned.m16n8k8.row.col.f32.tf32.tf32.f32 "
        "{%0,%1,%2,%3}, {%4,%5,%6,%7}, {%8,%9}, {%0,%1,%2,%3};"
        : "+f"(d[0]), "+f"(d[1]), "+f"(d[2]), "+f"(d[3])
        : "r"(a[0]), "r"(a[1]), "r"(a[2]), "r"(a[3]), "r"(b0), "r"(b1));
}
#define CP_ASYNC16(dst, src) \
    asm volatile("cp.async.cg.shared.global [%0], [%1], 16;" :: "r"(dst), "l"(src))
#define CP_COMMIT() asm volatile("cp.async.commit_group;" ::: "memory")
#define CP_WAIT1()  asm volatile("cp.async.wait_group 1;" ::: "memory")

// ---------------- GEMM smem layout (floats / bytes) ----------------
#define A_ST 36                       // padded A row stride (floats)
#define B_ST 264                      // padded B row stride (floats)
#define ABUF (128 * A_ST * 4)         // 18432 B
#define BBUF (32 * B_ST * 4)          // 33792 B
#define OFF_A(b) ((b) * ABUF)
#define OFF_B(b) (3 * ABUF + (b) * BBUF)
#define SMEM_GEMM (3 * ABUF + 3 * BBUF)   // 156672 B

// ===========================================================================
// Fused 3xTF32 GEMM: T[B,256] = [h | x] @ W[4352,256]
// CTA 128x256, BK=32, 256 threads (8 warps, warp tile 64x64),
// 3-stage cp.async ring, raw fp32 in smem, tf32 split in registers,
// MMA passes ordered for accumulator independence.
// ===========================================================================
__global__ __launch_bounds__(256, 1)
void gemm_fused(const float* __restrict__ Xh, const float* __restrict__ Xx,
                const float* __restrict__ W, float* __restrict__ C)
{
    extern __shared__ __align__(128) char smem[];
    const uint32_t sb = smem_u32(smem);

    const int tid  = threadIdx.x;
    const int warp = tid >> 5;
    const int lane = tid & 31;
    const int g    = lane >> 2;
    const int tg   = lane & 3;
    const int wm   = (warp >> 2) * 64;
    const int wn   = (warp & 3) * 64;
    const int m0   = blockIdx.x * 128;

    float d[4][8][4];
#pragma unroll
    for (int mt = 0; mt < 4; mt++)
#pragma unroll
        for (int nt = 0; nt < 8; nt++)
#pragma unroll
            for (int q = 0; q < 4; q++) d[mt][nt][q] = 0.f;

    auto issue = [&](int s) {
        const int k0  = s * 32;
        const int buf = s % 3;
        uint32_t abase = sb + OFF_A(buf);
#pragma unroll
        for (int i = 0; i < 4; i++) {
            int lin = i * 256 + tid;
            int row = lin >> 3;
            int c4  = lin & 7;
            int kg  = k0 + c4 * 4;
            const float* src = (kg < RDIM)
                ? (Xh + (size_t)(m0 + row) * RDIM + kg)
                : (Xx + (size_t)(m0 + row) * HID + (kg - RDIM));
            CP_ASYNC16(abase + (uint32_t)(row * A_ST + c4 * 4) * 4, src);
        }
        uint32_t bbase = sb + OFF_B(buf);
#pragma unroll
        for (int i = 0; i < 8; i++) {
            int lin = i * 256 + tid;
            int kr  = lin >> 6;
            int c16 = lin & 63;
            CP_ASYNC16(bbase + (uint32_t)(kr * B_ST + c16 * 4) * 4,
                       W + (size_t)(k0 + kr) * 256 + c16 * 4);
        }
        CP_COMMIT();
    };

    auto compute = [&](int buf) {
        const float* As = (const float*)(smem + OFF_A(buf));
        const float* Bs = (const float*)(smem + OFF_B(buf));
#pragma unroll
        for (int k8 = 0; k8 < 4; k8++) {
            const int kk = k8 * 8;
            uint32_t fah[4][4], fal[4][4];
#pragma unroll
            for (int mt = 0; mt < 4; mt++) {
                int base = (wm + mt * 16 + g) * A_ST + kk + tg;
                float r0 = As[base];
                float r1 = As[base + 8 * A_ST];
                float r2 = As[base + 4];
                float r3 = As[base + 8 * A_ST + 4];
                split_tf32(r0, fah[mt][0], fal[mt][0]);
                split_tf32(r1, fah[mt][1], fal[mt][1]);
                split_tf32(r2, fah[mt][2], fal[mt][2]);
                split_tf32(r3, fah[mt][3], fal[mt][3]);
            }
            uint32_t bh[8][2], bl[8][2];
#pragma unroll
            for (int nt = 0; nt < 8; nt++) {
                int nb = wn + nt * 8 + g;
                float r0 = Bs[(kk + tg) * B_ST + nb];
                float r1 = Bs[(kk + tg + 4) * B_ST + nb];
                split_tf32(r0, bh[nt][0], bl[nt][0]);
                split_tf32(r1, bh[nt][1], bl[nt][1]);
            }
            // pass 1: hi*hi  (32 independent accumulators between reuses)
#pragma unroll
            for (int nt = 0; nt < 8; nt++)
#pragma unroll
                for (int mt = 0; mt < 4; mt++)
                    mma_tf32(d[mt][nt], fah[mt], bh[nt][0], bh[nt][1]);
            // pass 2: hi*lo
#pragma unroll
            for (int nt = 0; nt < 8; nt++)
#pragma unroll
                for (int mt = 0; mt < 4; mt++)
                    mma_tf32(d[mt][nt], fah[mt], bl[nt][0], bl[nt][1]);
            // pass 3: lo*hi
#pragma unroll
            for (int nt = 0; nt < 8; nt++)
#pragma unroll
                for (int mt = 0; mt < 4; mt++)
                    mma_tf32(d[mt][nt], fal[mt], bh[nt][0], bh[nt][1]);
        }
    };

    // ---- 3-stage pipeline ----
    issue(0);
    issue(1);
    for (int s = 0; s < NS; s++) {
        CP_WAIT1();            // stage s complete (s+1 may stay in flight)
        __syncthreads();       // everyone done with compute(s-1); smem for s visible
        if (s + 2 < NS) issue(s + 2); else CP_COMMIT();
        compute(s % 3);
    }

    // ---- writeback ----
#pragma unroll
    for (int mt = 0; mt < 4; mt++) {
        int r0 = m0 + wm + mt * 16 + g;
#pragma unroll
        for (int nt = 0; nt < 8; nt++) {
            int c0 = wn + nt * 8 + tg * 2;
            *reinterpret_cast<float2*>(C + (size_t)r0 * 256 + c0) =
                make_float2(d[mt][nt][0], d[mt][nt][1]);
            *reinterpret_cast<float2*>(C + (size_t)(r0 + 8) * 256 + c0) =
                make_float2(d[mt][nt][2], d[mt][nt][3]);
        }
    }
}

// ===========================================================================
// Prep: g_W = [A ; Wp@Bm], g_c = bp@Bm.   grid=HID, 256 threads.
// ===========================================================================
__global__ void k_prep(const float* __restrict__ Wp, const float* __restrict__ Bm,
                       const float* __restrict__ A, const float* __restrict__ bp)
{
    __shared__ float srow[RDIM];
    int i = blockIdx.x, j = threadIdx.x;
    srow[j] = Wp[(size_t)i * RDIM + j];
    __syncthreads();
    float acc = 0.f;
#pragma unroll 8
    for (int k = 0; k < RDIM; k++)
        acc = fmaf(srow[k], Bm[k * RDIM + j], acc);
    g_W[(size_t)(RDIM + i) * RDIM + j] = acc;
    if (i < RDIM)
        g_W[(size_t)i * RDIM + j] = A[(size_t)i * RDIM + j];
    if (i == 0) {
        float c = 0.f;
#pragma unroll 8
        for (int k = 0; k < RDIM; k++)
            c = fmaf(bp[k], Bm[k * RDIM + j], c);
        g_c[j] = c;
    }
}

// ===========================================================================
// Epilogue: 32 rows/block. h_new = h + 0.1*(-h/tau + tanh(T + c));
// logits = h_new @ Wg + bg; +0.1 at prev_sel; top-2; softmax.
// smem: sWgT [64][260] | sH [32][260] | sL [32][64]
// ===========================================================================
#define EROWS   32
#define WG_ST   260
#define SMEM_EPI (64 * WG_ST * 4 + EROWS * WG_ST * 4 + EROWS * 64 * 4)  // 108032
__global__ __launch_bounds__(256)
void k_epi(const float* __restrict__ h, const int* __restrict__ prev_sel,
           const float* __restrict__ tau, const float* __restrict__ Wg,
           const float* __restrict__ bg, float* __restrict__ out, int B)
{
    extern __shared__ __align__(16) char esm[];
    float* sWgT = (float*)esm;                          // [64][260] (WgT[e][k])
    float* sH   = (float*)(esm + 64 * WG_ST * 4);       // [32][260]
    float* sL   = (float*)(esm + (64 + EROWS) * WG_ST * 4); // [32][64]
    const int tid = threadIdx.x;
    const size_t r0 = (size_t)blockIdx.x * EROWS;

    // transpose Wg into smem
#pragma unroll
    for (int i = 0; i < 64; i++) {
        int f = i * 256 + tid;
        int k = f >> 6, e = f & 63;
        sWgT[e * WG_ST + k] = Wg[f];
    }
    // tanh update: thread owns column `tid` across all 32 rows
    {
        float tauv = tau[tid];
        float cv   = g_c[tid];
#pragma unroll
        for (int row = 0; row < EROWS; row++) {
            size_t gidx = (r0 + row) * 256 + tid;
            float hj = h[gidx];
            float Tj = g_T[gidx];
            sH[row * WG_ST + tid] = hj + 0.1f * (-hj / tauv + tanhf(Tj + cv));
        }
    }
    __syncthreads();

    // logits: thread -> (e = tid&63, rows rbase+4i)
    {
        const int e = tid & 63;
        const int rbase = tid >> 6;   // 0..3
        float acc[8];
#pragma unroll
        for (int i = 0; i < 8; i++) acc[i] = 0.f;
        const float* wrow = sWgT + e * WG_ST;
#pragma unroll 4
        for (int k4 = 0; k4 < 64; k4++) {
            float4 w = *reinterpret_cast<const float4*>(wrow + k4 * 4);
#pragma unroll
            for (int i = 0; i < 8; i++) {
                const float* hr = sH + (rbase + 4 * i) * WG_ST + k4 * 4;
                float4 hv = *reinterpret_cast<const float4*>(hr);
                acc[i] = fmaf(hv.x, w.x, acc[i]);
                acc[i] = fmaf(hv.y, w.y, acc[i]);
                acc[i] = fmaf(hv.z, w.z, acc[i]);
                acc[i] = fmaf(hv.w, w.w, acc[i]);
            }
        }
        float bgv = bg[e];
#pragma unroll
        for (int i = 0; i < 8; i++)
            sL[(rbase + 4 * i) * 64 + e] = acc[i] + bgv;
    }
    __syncthreads();

    if (tid < EROWS) {
        int row = tid;
        int p0 = prev_sel[(r0 + row) * 2 + 0];
        int p1 = prev_sel[(r0 + row) * 2 + 1];
        float v1 = -1e30f, v2 = -1e30f;
        int i1 = 0, i2 = 0;
#pragma unroll
        for (int q = 0; q < 64; q++) {
            float v = sL[row * 64 + q] + ((q == p0 || q == p1) ? 0.1f : 0.f);
            if (v > v1) { v2 = v1; i2 = i1; v1 = v; i1 = q; }
            else if (v > v2) { v2 = v; i2 = q; }
        }
        float e2 = expf(v2 - v1);
        float sm = 1.f + e2;
        size_t orow = r0 + row;
        out[orow * 2 + 0] = (float)i1;
        out[orow * 2 + 1] = (float)i2;
        size_t woff = (size_t)2 * B;
        out[woff + orow * 2 + 0] = 1.f / sm;
        out[woff + orow * 2 + 1] = e2 / sm;
    }
}

// ===========================================================================
extern "C" void kernel_launch(void* const* d_in, const int* in_sizes, int n_in,
                              void* d_out, int out_size)
{
    const float *x = 0, *h = 0, *Wp = 0, *bp = 0, *tau = 0, *A = 0, *Bm = 0,
                *Wg = 0, *bg = 0;
    const int* prev_sel = 0;
    for (int i = 0; i < n_in; i++) {
        int s = in_sizes[i];
        const void* pv = d_in[i];
        switch (s) {
            case BATCH * HID:  x = (const float*)pv; break;
            case BATCH * RDIM: h = (const float*)pv; break;
            case BATCH * TOPK: prev_sel = (const int*)pv; break;
            case HID * RDIM:   Wp = (const float*)pv; break;
            case RDIM:         if (!bp) bp = (const float*)pv; else tau = (const float*)pv; break;
            case RDIM * RDIM:  if (!A) A = (const float*)pv; else Bm = (const float*)pv; break;
            case RDIM * EDIM:  Wg = (const float*)pv; break;
            case EDIM:         bg = (const float*)pv; break;
            default: break;
        }
    }
    if (!x)        x        = (const float*)d_in[0];
    if (!h)        h        = (const float*)d_in[1];
    if (!prev_sel) prev_sel = (const int*)d_in[2];
    if (!Wp)       Wp       = (const float*)d_in[3];
    if (!bp)       bp       = (const float*)d_in[4];
    if (!tau)      tau      = (const float*)d_in[5];
    if (!A)        A        = (const float*)d_in[6];
    if (!Bm)       Bm       = (const float*)d_in[7];
    if (!Wg)       Wg       = (const float*)d_in[8];
    if (!bg)       bg       = (const float*)d_in[9];

    static int attr_done = 0;
    if (!attr_done) {
        cudaFuncSetAttribute(gemm_fused, cudaFuncAttributeMaxDynamicSharedMemorySize, SMEM_GEMM);
        cudaFuncSetAttribute(k_epi, cudaFuncAttributeMaxDynamicSharedMemorySize, SMEM_EPI);
        attr_done = 1;
    }

    float *Wptr = 0, *Tp = 0;
    cudaGetSymbolAddress((void**)&Wptr, g_W);
    cudaGetSymbolAddress((void**)&Tp, g_T);
    float* out = (float*)d_out;

    // 1) g_W = [A ; Wp@Bm], g_c = bp@Bm
    k_prep<<<HID, 256>>>(Wp, Bm, A, bp);
    // 2) T = [h | x] @ g_W   (3xTF32, K=4352)
    gemm_fused<<<BATCH / 128, 256, SMEM_GEMM>>>(h, x, Wptr, Tp);
    // 3) epilogue
    k_epi<<<BATCH / EROWS, 256, SMEM_EPI>>>(h, prev_sel, tau, Wg, bg, out, BATCH);
}

// round 6
// speedup vs baseline: 1.5505x; 1.0544x over previous
#include <cuda_runtime.h>
#include <cstdint>

#define BATCH 65536
#define HID   4096
#define RDIM  256
#define EDIM  64
#define TOPK  2
#define KTOT  (RDIM + HID)        // 4352
#define NS    (KTOT / 32)         // 136 stages

// ---------------- device scratch ----------------
__device__ float g_W[(size_t)KTOT * RDIM];   // [A ; Wp@Bm] stacked, [K][256]
__device__ float g_c[RDIM];                  // bp @ Bm
__device__ float g_T[(size_t)BATCH * RDIM];  // h@A + x@Wf

// ---------------- helpers ----------------
__device__ __forceinline__ uint32_t smem_u32(const void* p) {
    uint32_t a;
    asm("{ .reg .u64 t; cvta.to.shared.u64 t, %1; cvt.u32.u64 %0, t; }"
        : "=r"(a) : "l"(p));
    return a;
}
__device__ __forceinline__ void split_tf32(float v, uint32_t& hi, uint32_t& lo) {
    uint32_t u;
    asm("cvt.rna.tf32.f32 %0, %1;" : "=r"(u) : "f"(v));
    hi = u;
    float r = v - __uint_as_float(u);
    asm("cvt.rna.tf32.f32 %0, %1;" : "=r"(lo) : "f"(r));
}
__device__ __forceinline__ void mma_tf32(float d[4],
                                         const uint32_t a[4],
                                         uint32_t b0, uint32_t b1) {
    asm volatile(
        "mma.sync.aligned.m16n8k8.row.col.f32.tf32.tf32.f32 "
        "{%0,%1,%2,%3}, {%4,%5,%6,%7}, {%8,%9}, {%0,%1,%2,%3};"
        : "+f"(d[0]), "+f"(d[1]), "+f"(d[2]), "+f"(d[3])
        : "r"(a[0]), "r"(a[1]), "r"(a[2]), "r"(a[3]), "r"(b0), "r"(b1));
}
#define CP_ASYNC16(dst, src) \
    asm volatile("cp.async.cg.shared.global [%0], [%1], 16;" :: "r"(dst), "l"(src))
#define CP_COMMIT() asm volatile("cp.async.commit_group;" ::: "memory")
#define CP_WAIT1()  asm volatile("cp.async.wait_group 1;" ::: "memory")

// ---------------- GEMM smem layout ----------------
#define A_ST 36                       // padded A row stride (floats)
#define B_ST 136                      // padded B row stride (floats)
#define ABUF (128 * A_ST * 4)         // 18432 B
#define BBUF (32 * B_ST * 4)          // 17408 B
#define OFF_A(b) ((b) * ABUF)
#define OFF_B(b) (3 * ABUF + (b) * BBUF)
#define SMEM_GEMM (3 * ABUF + 3 * BBUF)   // 107520 B -> 2 CTAs/SM

// ===========================================================================
// Fused 3xTF32 GEMM: T[B,256] = [h | x] @ W[4352,256]
// CTA 128(M) x 128(N), BK=32, 256 threads, warp tile 64x32,
// 3-stage cp.async ring, 2 CTAs/SM. Per-output accumulation order is
// identical to the previous round (hi*hi, hi*lo, lo*hi per k8, k8 ascending).
// ===========================================================================
__global__ __launch_bounds__(256, 2)
void gemm_fused(const float* __restrict__ Xh, const float* __restrict__ Xx,
                const float* __restrict__ W, float* __restrict__ C)
{
    extern __shared__ __align__(128) char smem[];
    const uint32_t sb = smem_u32(smem);

    const int tid  = threadIdx.x;
    const int warp = tid >> 5;
    const int lane = tid & 31;
    const int g    = lane >> 2;
    const int tg   = lane & 3;
    const int wm   = (warp >> 2) * 64;       // 0 / 64
    const int wn   = (warp & 3) * 32;        // 0 / 32 / 64 / 96
    const int m0   = blockIdx.x * 128;
    const int n0   = blockIdx.y * 128;

    float d[4][4][4];
#pragma unroll
    for (int mt = 0; mt < 4; mt++)
#pragma unroll
        for (int nt = 0; nt < 4; nt++)
#pragma unroll
            for (int q = 0; q < 4; q++) d[mt][nt][q] = 0.f;

    auto issue = [&](int s) {
        const int k0  = s * 32;
        const int buf = s % 3;
        uint32_t abase = sb + OFF_A(buf);
#pragma unroll
        for (int i = 0; i < 4; i++) {
            int lin = i * 256 + tid;          // 0..1023
            int row = lin >> 3;               // 0..127
            int c4  = lin & 7;                // 0..7
            int kg  = k0 + c4 * 4;
            const float* src = (kg < RDIM)
                ? (Xh + (size_t)(m0 + row) * RDIM + kg)
                : (Xx + (size_t)(m0 + row) * HID + (kg - RDIM));
            CP_ASYNC16(abase + (uint32_t)(row * A_ST + c4 * 4) * 4, src);
        }
        uint32_t bbase = sb + OFF_B(buf);
#pragma unroll
        for (int i = 0; i < 4; i++) {
            int lin = i * 256 + tid;          // 0..1023
            int kr  = lin >> 5;               // 0..31
            int c16 = lin & 31;               // 0..31 (float4 cols)
            CP_ASYNC16(bbase + (uint32_t)(kr * B_ST + c16 * 4) * 4,
                       W + (size_t)(k0 + kr) * 256 + n0 + c16 * 4);
        }
        CP_COMMIT();
    };

    auto compute = [&](int buf) {
        const float* As = (const float*)(smem + OFF_A(buf));
        const float* Bs = (const float*)(smem + OFF_B(buf));
#pragma unroll
        for (int k8 = 0; k8 < 4; k8++) {
            const int kk = k8 * 8;
            uint32_t bh[4][2], bl[4][2];
#pragma unroll
            for (int nt = 0; nt < 4; nt++) {
                int nb = wn + nt * 8 + g;
                split_tf32(Bs[(kk + tg) * B_ST + nb],     bh[nt][0], bl[nt][0]);
                split_tf32(Bs[(kk + tg + 4) * B_ST + nb], bh[nt][1], bl[nt][1]);
            }
#pragma unroll
            for (int mh = 0; mh < 2; mh++) {
                uint32_t fah[2][4], fal[2][4];
#pragma unroll
                for (int mi = 0; mi < 2; mi++) {
                    int mt = mh * 2 + mi;
                    int base = (wm + mt * 16 + g) * A_ST + kk + tg;
                    split_tf32(As[base],                fah[mi][0], fal[mi][0]);
                    split_tf32(As[base + 8 * A_ST],     fah[mi][1], fal[mi][1]);
                    split_tf32(As[base + 4],            fah[mi][2], fal[mi][2]);
                    split_tf32(As[base + 8 * A_ST + 4], fah[mi][3], fal[mi][3]);
                }
                // pass-major (8 independent accumulators between reuses);
                // per-output order remains hihi -> hilo -> lohi within k8
#pragma unroll
                for (int nt = 0; nt < 4; nt++)
#pragma unroll
                    for (int mi = 0; mi < 2; mi++)
                        mma_tf32(d[mh * 2 + mi][nt], fah[mi], bh[nt][0], bh[nt][1]);
#pragma unroll
                for (int nt = 0; nt < 4; nt++)
#pragma unroll
                    for (int mi = 0; mi < 2; mi++)
                        mma_tf32(d[mh * 2 + mi][nt], fah[mi], bl[nt][0], bl[nt][1]);
#pragma unroll
                for (int nt = 0; nt < 4; nt++)
#pragma unroll
                    for (int mi = 0; mi < 2; mi++)
                        mma_tf32(d[mh * 2 + mi][nt], fal[mi], bh[nt][0], bh[nt][1]);
            }
        }
    };

    // ---- 3-stage pipeline ----
    issue(0);
    issue(1);
    for (int s = 0; s < NS; s++) {
        CP_WAIT1();
        __syncthreads();
        if (s + 2 < NS) issue(s + 2); else CP_COMMIT();
        compute(s % 3);
    }

    // ---- writeback ----
#pragma unroll
    for (int mt = 0; mt < 4; mt++) {
        int r0 = m0 + wm + mt * 16 + g;
#pragma unroll
        for (int nt = 0; nt < 4; nt++) {
            int c0 = n0 + wn + nt * 8 + tg * 2;
            *reinterpret_cast<float2*>(C + (size_t)r0 * 256 + c0) =
                make_float2(d[mt][nt][0], d[mt][nt][1]);
            *reinterpret_cast<float2*>(C + (size_t)(r0 + 8) * 256 + c0) =
                make_float2(d[mt][nt][2], d[mt][nt][3]);
        }
    }
}

// ===========================================================================
// Prep: g_W = [A ; Wp@Bm], g_c = bp@Bm.   grid=HID, 256 threads.
// ===========================================================================
__global__ void k_prep(const float* __restrict__ Wp, const float* __restrict__ Bm,
                       const float* __restrict__ A, const float* __restrict__ bp)
{
    __shared__ float srow[RDIM];
    int i = blockIdx.x, j = threadIdx.x;
    srow[j] = Wp[(size_t)i * RDIM + j];
    __syncthreads();
    float acc = 0.f;
#pragma unroll 8
    for (int k = 0; k < RDIM; k++)
        acc = fmaf(srow[k], Bm[k * RDIM + j], acc);
    g_W[(size_t)(RDIM + i) * RDIM + j] = acc;
    if (i < RDIM)
        g_W[(size_t)i * RDIM + j] = A[(size_t)i * RDIM + j];
    if (i == 0) {
        float c = 0.f;
#pragma unroll 8
        for (int k = 0; k < RDIM; k++)
            c = fmaf(bp[k], Bm[k * RDIM + j], c);
        g_c[j] = c;
    }
}

// ===========================================================================
// Epilogue: 32 rows/block. h_new = h + 0.1*(-h/tau + tanh(T + c));
// logits = h_new @ Wg + bg; +0.1 at prev_sel; top-2; softmax.
// ===========================================================================
#define EROWS   32
#define WG_ST   260
#define SMEM_EPI (64 * WG_ST * 4 + EROWS * WG_ST * 4 + EROWS * 64 * 4)  // 108032
__global__ __launch_bounds__(256)
void k_epi(const float* __restrict__ h, const int* __restrict__ prev_sel,
           const float* __restrict__ tau, const float* __restrict__ Wg,
           const float* __restrict__ bg, float* __restrict__ out, int B)
{
    extern __shared__ __align__(16) char esm[];
    float* sWgT = (float*)esm;                              // [64][260]
    float* sH   = (float*)(esm + 64 * WG_ST * 4);           // [32][260]
    float* sL   = (float*)(esm + (64 + EROWS) * WG_ST * 4); // [32][64]
    const int tid = threadIdx.x;
    const size_t r0 = (size_t)blockIdx.x * EROWS;

#pragma unroll
    for (int i = 0; i < 64; i++) {
        int f = i * 256 + tid;
        int k = f >> 6, e = f & 63;
        sWgT[e * WG_ST + k] = Wg[f];
    }
    {
        float tauv = tau[tid];
        float cv   = g_c[tid];
#pragma unroll
        for (int row = 0; row < EROWS; row++) {
            size_t gidx = (r0 + row) * 256 + tid;
            float hj = h[gidx];
            float Tj = g_T[gidx];
            sH[row * WG_ST + tid] = hj + 0.1f * (-hj / tauv + tanhf(Tj + cv));
        }
    }
    __syncthreads();

    {
        const int e = tid & 63;
        const int rbase = tid >> 6;
        float acc[8];
#pragma unroll
        for (int i = 0; i < 8; i++) acc[i] = 0.f;
        const float* wrow = sWgT + e * WG_ST;
#pragma unroll 4
        for (int k4 = 0; k4 < 64; k4++) {
            float4 w = *reinterpret_cast<const float4*>(wrow + k4 * 4);
#pragma unroll
            for (int i = 0; i < 8; i++) {
                const float* hr = sH + (rbase + 4 * i) * WG_ST + k4 * 4;
                float4 hv = *reinterpret_cast<const float4*>(hr);
                acc[i] = fmaf(hv.x, w.x, acc[i]);
                acc[i] = fmaf(hv.y, w.y, acc[i]);
                acc[i] = fmaf(hv.z, w.z, acc[i]);
                acc[i] = fmaf(hv.w, w.w, acc[i]);
            }
        }
        float bgv = bg[e];
#pragma unroll
        for (int i = 0; i < 8; i++)
            sL[(rbase + 4 * i) * 64 + e] = acc[i] + bgv;
    }
    __syncthreads();

    if (tid < EROWS) {
        int row = tid;
        int p0 = prev_sel[(r0 + row) * 2 + 0];
        int p1 = prev_sel[(r0 + row) * 2 + 1];
        float v1 = -1e30f, v2 = -1e30f;
        int i1 = 0, i2 = 0;
#pragma unroll
        for (int q = 0; q < 64; q++) {
            float v = sL[row * 64 + q] + ((q == p0 || q == p1) ? 0.1f : 0.f);
            if (v > v1) { v2 = v1; i2 = i1; v1 = v; i1 = q; }
            else if (v > v2) { v2 = v; i2 = q; }
        }
        float e2 = expf(v2 - v1);
        float sm = 1.f + e2;
        size_t orow = r0 + row;
        out[orow * 2 + 0] = (float)i1;
        out[orow * 2 + 1] = (float)i2;
        size_t woff = (size_t)2 * B;
        out[woff + orow * 2 + 0] = 1.f / sm;
        out[woff + orow * 2 + 1] = e2 / sm;
    }
}

// ===========================================================================
extern "C" void kernel_launch(void* const* d_in, const int* in_sizes, int n_in,
                              void* d_out, int out_size)
{
    const float *x = 0, *h = 0, *Wp = 0, *bp = 0, *tau = 0, *A = 0, *Bm = 0,
                *Wg = 0, *bg = 0;
    const int* prev_sel = 0;
    for (int i = 0; i < n_in; i++) {
        int s = in_sizes[i];
        const void* pv = d_in[i];
        switch (s) {
            case BATCH * HID:  x = (const float*)pv; break;
            case BATCH * RDIM: h = (const float*)pv; break;
            case BATCH * TOPK: prev_sel = (const int*)pv; break;
            case HID * RDIM:   Wp = (const float*)pv; break;
            case RDIM:         if (!bp) bp = (const float*)pv; else tau = (const float*)pv; break;
            case RDIM * RDIM:  if (!A) A = (const float*)pv; else Bm = (const float*)pv; break;
            case RDIM * EDIM:  Wg = (const float*)pv; break;
            case EDIM:         bg = (const float*)pv; break;
            default: break;
        }
    }
    if (!x)        x        = (const float*)d_in[0];
    if (!h)        h        = (const float*)d_in[1];
    if (!prev_sel) prev_sel = (const int*)d_in[2];
    if (!Wp)       Wp       = (const float*)d_in[3];
    if (!bp)       bp       = (const float*)d_in[4];
    if (!tau)      tau      = (const float*)d_in[5];
    if (!A)        A        = (const float*)d_in[6];
    if (!Bm)       Bm       = (const float*)d_in[7];
    if (!Wg)       Wg       = (const float*)d_in[8];
    if (!bg)       bg       = (const float*)d_in[9];

    static int attr_done = 0;
    if (!attr_done) {
        cudaFuncSetAttribute(gemm_fused, cudaFuncAttributeMaxDynamicSharedMemorySize, SMEM_GEMM);
        cudaFuncSetAttribute(k_epi, cudaFuncAttributeMaxDynamicSharedMemorySize, SMEM_EPI);
        attr_done = 1;
    }

    float *Wptr = 0, *Tp = 0;
    cudaGetSymbolAddress((void**)&Wptr, g_W);
    cudaGetSymbolAddress((void**)&Tp, g_T);
    float* out = (float*)d_out;

    // 1) g_W = [A ; Wp@Bm], g_c = bp@Bm
    k_prep<<<HID, 256>>>(Wp, Bm, A, bp);
    // 2) T = [h | x] @ g_W   (3xTF32, K=4352), 2 CTAs/SM
    dim3 grid(BATCH / 128, 2);
    gemm_fused<<<grid, 256, SMEM_GEMM>>>(h, x, Wptr, Tp);
    // 3) epilogue
    k_epi<<<BATCH / EROWS, 256, SMEM_EPI>>>(h, prev_sel, tau, Wg, bg, out, BATCH);
}

// round 7
// speedup vs baseline: 2.0848x; 1.3446x over previous
#include <cuda_runtime.h>
#include <cstdint>

#define BATCH 65536
#define HID   4096
#define RDIM  256
#define EDIM  64
#define TOPK  2
#define KTOT  (RDIM + HID)        // 4352
#define NS    (KTOT / 32)         // 136 stages
#define THR   4e-3f               // ambiguity threshold on logit gaps

// ---------------- device scratch ----------------
__device__ float g_W[(size_t)KTOT * RDIM];   // [A ; Wp@Bm] stacked, [K][256]
__device__ float g_c[RDIM];                  // bp @ Bm
__device__ float g_T[(size_t)BATCH * RDIM];  // h@A + x@Wf
__device__ int   g_cnt;                      // # ambiguous rows
__device__ int   g_rows[BATCH];              // ambiguous row ids

// ---------------- helpers ----------------
__device__ __forceinline__ uint32_t smem_u32(const void* p) {
    uint32_t a;
    asm("{ .reg .u64 t; cvta.to.shared.u64 t, %1; cvt.u32.u64 %0, t; }"
        : "=r"(a) : "l"(p));
    return a;
}
__device__ __forceinline__ uint32_t to_tf32(float v) {
    uint32_t u;
    asm("cvt.rna.tf32.f32 %0, %1;" : "=r"(u) : "f"(v));
    return u;
}
__device__ __forceinline__ void mma_tf32(float d[4],
                                         const uint32_t a[4],
                                         uint32_t b0, uint32_t b1) {
    asm volatile(
        "mma.sync.aligned.m16n8k8.row.col.f32.tf32.tf32.f32 "
        "{%0,%1,%2,%3}, {%4,%5,%6,%7}, {%8,%9}, {%0,%1,%2,%3};"
        : "+f"(d[0]), "+f"(d[1]), "+f"(d[2]), "+f"(d[3])
        : "r"(a[0]), "r"(a[1]), "r"(a[2]), "r"(a[3]), "r"(b0), "r"(b1));
}
#define CP_ASYNC16(dst, src) \
    asm volatile("cp.async.cg.shared.global [%0], [%1], 16;" :: "r"(dst), "l"(src))
#define CP_COMMIT() asm volatile("cp.async.commit_group;" ::: "memory")
#define CP_WAIT1()  asm volatile("cp.async.wait_group 1;" ::: "memory")

// ---------------- GEMM smem layout ----------------
#define A_ST 36
#define B_ST 136
#define ABUF (128 * A_ST * 4)         // 18432 B
#define BBUF (32 * B_ST * 4)          // 17408 B
#define OFF_A(b) ((b) * ABUF)
#define OFF_B(b) (3 * ABUF + (b) * BBUF)
#define SMEM_GEMM (3 * ABUF + 3 * BBUF)   // 107520 B -> 2 CTAs/SM

// ===========================================================================
// Single-pass TF32 GEMM: T[B,256] = [h | x] @ W[4352,256]  (rna-rounded tf32)
// CTA 128(M) x 128(N), BK=32, 256 threads, warp tile 64x32,
// 3-stage cp.async ring, 2 CTAs/SM.
// ===========================================================================
__global__ __launch_bounds__(256, 2)
void gemm_fused(const float* __restrict__ Xh, const float* __restrict__ Xx,
                const float* __restrict__ W, float* __restrict__ C)
{
    extern __shared__ __align__(128) char smem[];
    const uint32_t sb = smem_u32(smem);

    const int tid  = threadIdx.x;
    const int warp = tid >> 5;
    const int lane = tid & 31;
    const int g    = lane >> 2;
    const int tg   = lane & 3;
    const int wm   = (warp >> 2) * 64;
    const int wn   = (warp & 3) * 32;
    const int m0   = blockIdx.x * 128;
    const int n0   = blockIdx.y * 128;

    float d[4][4][4];
#pragma unroll
    for (int mt = 0; mt < 4; mt++)
#pragma unroll
        for (int nt = 0; nt < 4; nt++)
#pragma unroll
            for (int q = 0; q < 4; q++) d[mt][nt][q] = 0.f;

    auto issue = [&](int s) {
        const int k0  = s * 32;
        const int buf = s % 3;
        uint32_t abase = sb + OFF_A(buf);
#pragma unroll
        for (int i = 0; i < 4; i++) {
            int lin = i * 256 + tid;
            int row = lin >> 3;
            int c4  = lin & 7;
            int kg  = k0 + c4 * 4;
            const float* src = (kg < RDIM)
                ? (Xh + (size_t)(m0 + row) * RDIM + kg)
                : (Xx + (size_t)(m0 + row) * HID + (kg - RDIM));
            CP_ASYNC16(abase + (uint32_t)(row * A_ST + c4 * 4) * 4, src);
        }
        uint32_t bbase = sb + OFF_B(buf);
#pragma unroll
        for (int i = 0; i < 4; i++) {
            int lin = i * 256 + tid;
            int kr  = lin >> 5;
            int c16 = lin & 31;
            CP_ASYNC16(bbase + (uint32_t)(kr * B_ST + c16 * 4) * 4,
                       W + (size_t)(k0 + kr) * 256 + n0 + c16 * 4);
        }
        CP_COMMIT();
    };

    auto compute = [&](int buf) {
        const float* As = (const float*)(smem + OFF_A(buf));
        const float* Bs = (const float*)(smem + OFF_B(buf));
#pragma unroll
        for (int k8 = 0; k8 < 4; k8++) {
            const int kk = k8 * 8;
            uint32_t bh[4][2];
#pragma unroll
            for (int nt = 0; nt < 4; nt++) {
                int nb = wn + nt * 8 + g;
                bh[nt][0] = to_tf32(Bs[(kk + tg) * B_ST + nb]);
                bh[nt][1] = to_tf32(Bs[(kk + tg + 4) * B_ST + nb]);
            }
#pragma unroll
            for (int mh = 0; mh < 2; mh++) {
                uint32_t fah[2][4];
#pragma unroll
                for (int mi = 0; mi < 2; mi++) {
                    int mt = mh * 2 + mi;
                    int base = (wm + mt * 16 + g) * A_ST + kk + tg;
                    fah[mi][0] = to_tf32(As[base]);
                    fah[mi][1] = to_tf32(As[base + 8 * A_ST]);
                    fah[mi][2] = to_tf32(As[base + 4]);
                    fah[mi][3] = to_tf32(As[base + 8 * A_ST + 4]);
                }
#pragma unroll
                for (int nt = 0; nt < 4; nt++)
#pragma unroll
                    for (int mi = 0; mi < 2; mi++)
                        mma_tf32(d[mh * 2 + mi][nt], fah[mi], bh[nt][0], bh[nt][1]);
            }
        }
    };

    issue(0);
    issue(1);
    for (int s = 0; s < NS; s++) {
        CP_WAIT1();
        __syncthreads();
        if (s + 2 < NS) issue(s + 2); else CP_COMMIT();
        compute(s % 3);
    }

#pragma unroll
    for (int mt = 0; mt < 4; mt++) {
        int r0 = m0 + wm + mt * 16 + g;
#pragma unroll
        for (int nt = 0; nt < 4; nt++) {
            int c0 = n0 + wn + nt * 8 + tg * 2;
            *reinterpret_cast<float2*>(C + (size_t)r0 * 256 + c0) =
                make_float2(d[mt][nt][0], d[mt][nt][1]);
            *reinterpret_cast<float2*>(C + (size_t)(r0 + 8) * 256 + c0) =
                make_float2(d[mt][nt][2], d[mt][nt][3]);
        }
    }
}

// ===========================================================================
// Prep: g_W = [A ; Wp@Bm], g_c = bp@Bm, zero ambiguity counter.
// ===========================================================================
__global__ void k_prep(const float* __restrict__ Wp, const float* __restrict__ Bm,
                       const float* __restrict__ A, const float* __restrict__ bp)
{
    __shared__ float srow[RDIM];
    int i = blockIdx.x, j = threadIdx.x;
    if (i == 0 && j == 0) g_cnt = 0;
    srow[j] = Wp[(size_t)i * RDIM + j];
    __syncthreads();
    float acc = 0.f;
#pragma unroll 8
    for (int k = 0; k < RDIM; k++)
        acc = fmaf(srow[k], Bm[k * RDIM + j], acc);
    g_W[(size_t)(RDIM + i) * RDIM + j] = acc;
    if (i < RDIM)
        g_W[(size_t)i * RDIM + j] = A[(size_t)i * RDIM + j];
    if (i == 0) {
        float c = 0.f;
#pragma unroll 8
        for (int k = 0; k < RDIM; k++)
            c = fmaf(bp[k], Bm[k * RDIM + j], c);
        g_c[j] = c;
    }
}

// ===========================================================================
// Epilogue: 32 rows/block; flags ambiguous rows (gap12 or gap23 < THR).
// ===========================================================================
#define EROWS   32
#define WG_ST   260
#define SMEM_EPI (64 * WG_ST * 4 + EROWS * WG_ST * 4 + EROWS * 64 * 4)  // 108032
__global__ __launch_bounds__(256)
void k_epi(const float* __restrict__ h, const int* __restrict__ prev_sel,
           const float* __restrict__ tau, const float* __restrict__ Wg,
           const float* __restrict__ bg, float* __restrict__ out, int B)
{
    extern __shared__ __align__(16) char esm[];
    float* sWgT = (float*)esm;                              // [64][260]
    float* sH   = (float*)(esm + 64 * WG_ST * 4);           // [32][260]
    float* sL   = (float*)(esm + (64 + EROWS) * WG_ST * 4); // [32][64]
    const int tid = threadIdx.x;
    const size_t r0 = (size_t)blockIdx.x * EROWS;

#pragma unroll
    for (int i = 0; i < 64; i++) {
        int f = i * 256 + tid;
        int k = f >> 6, e = f & 63;
        sWgT[e * WG_ST + k] = Wg[f];
    }
    {
        float tauv = tau[tid];
        float cv   = g_c[tid];
#pragma unroll
        for (int row = 0; row < EROWS; row++) {
            size_t gidx = (r0 + row) * 256 + tid;
            float hj = h[gidx];
            float Tj = g_T[gidx];
            sH[row * WG_ST + tid] = hj + 0.1f * (-hj / tauv + tanhf(Tj + cv));
        }
    }
    __syncthreads();

    {
        const int e = tid & 63;
        const int rbase = tid >> 6;
        float acc[8];
#pragma unroll
        for (int i = 0; i < 8; i++) acc[i] = 0.f;
        const float* wrow = sWgT + e * WG_ST;
#pragma unroll 4
        for (int k4 = 0; k4 < 64; k4++) {
            float4 w = *reinterpret_cast<const float4*>(wrow + k4 * 4);
#pragma unroll
            for (int i = 0; i < 8; i++) {
                const float* hr = sH + (rbase + 4 * i) * WG_ST + k4 * 4;
                float4 hv = *reinterpret_cast<const float4*>(hr);
                acc[i] = fmaf(hv.x, w.x, acc[i]);
                acc[i] = fmaf(hv.y, w.y, acc[i]);
                acc[i] = fmaf(hv.z, w.z, acc[i]);
                acc[i] = fmaf(hv.w, w.w, acc[i]);
            }
        }
        float bgv = bg[e];
#pragma unroll
        for (int i = 0; i < 8; i++)
            sL[(rbase + 4 * i) * 64 + e] = acc[i] + bgv;
    }
    __syncthreads();

    if (tid < EROWS) {
        int row = tid;
        size_t orow = r0 + row;
        int p0 = prev_sel[orow * 2 + 0];
        int p1 = prev_sel[orow * 2 + 1];
        float v1 = -1e30f, v2 = -1e30f, v3 = -1e30f;
        int i1 = 0, i2 = 0;
#pragma unroll
        for (int q = 0; q < 64; q++) {
            float v = sL[row * 64 + q] + ((q == p0 || q == p1) ? 0.1f : 0.f);
            if (v > v1)      { v3 = v2; v2 = v1; i2 = i1; v1 = v; i1 = q; }
            else if (v > v2) { v3 = v2; v2 = v; i2 = q; }
            else if (v > v3) { v3 = v; }
        }
        // flag ambiguous rows for exact fp32 recompute
        float gap = fminf(v1 - v2, v2 - v3);
        if (gap < THR) {
            int slot = atomicAdd(&g_cnt, 1);
            g_rows[slot] = (int)orow;
        }
        float e2 = expf(v2 - v1);
        float sm = 1.f + e2;
        out[orow * 2 + 0] = (float)i1;
        out[orow * 2 + 1] = (float)i2;
        size_t woff = (size_t)2 * B;
        out[woff + orow * 2 + 0] = 1.f / sm;
        out[woff + orow * 2 + 1] = e2 / sm;
    }
}

// ===========================================================================
// Fixup GEMM: exact fp32 T for flagged rows (gathered 64-row tiles, K=4352).
// ===========================================================================
__global__ __launch_bounds__(256)
void k_fixT(const float* __restrict__ h, const float* __restrict__ x,
            const float* __restrict__ W)
{
    const int nrows = g_cnt;
    const int m0 = blockIdx.x * 64;
    if (m0 >= nrows) return;

    __shared__ float sX[64][16];
    __shared__ float sW[16][256];
    __shared__ int   srows[64];

    const int tid = threadIdx.x;
    const int tx = tid & 31, ty = tid >> 5;
    const int xr = tid >> 2, xq = tid & 3;
    const int wr = tid >> 6, wc = tid & 63;

    if (tid < 64) {
        int idx = m0 + tid;
        srows[tid] = g_rows[idx < nrows ? idx : nrows - 1];
    }
    __syncthreads();

    float acc[8][8];
#pragma unroll
    for (int i = 0; i < 8; i++)
#pragma unroll
        for (int j = 0; j < 8; j++) acc[i][j] = 0.f;

    for (int k0 = 0; k0 < KTOT; k0 += 16) {
        {
            int row = srows[xr];
            int kg = k0 + xq * 4;
            const float* src = (kg < RDIM)
                ? (h + (size_t)row * RDIM + kg)
                : (x + (size_t)row * HID + (kg - RDIM));
            *reinterpret_cast<float4*>(&sX[xr][xq * 4]) =
                *reinterpret_cast<const float4*>(src);
        }
#pragma unroll
        for (int r = 0; r < 4; r++)
            *reinterpret_cast<float4*>(&sW[wr + 4 * r][wc * 4]) =
                *reinterpret_cast<const float4*>(W + (size_t)(k0 + wr + 4 * r) * 256 + wc * 4);
        __syncthreads();

#pragma unroll
        for (int k = 0; k < 16; k++) {
            float a[8], b[8];
#pragma unroll
            for (int i = 0; i < 8; i++) a[i] = sX[ty + 8 * i][k];
#pragma unroll
            for (int j = 0; j < 8; j++) b[j] = sW[k][tx + 32 * j];
#pragma unroll
            for (int i = 0; i < 8; i++)
#pragma unroll
                for (int j = 0; j < 8; j++)
                    acc[i][j] = fmaf(a[i], b[j], acc[i][j]);
        }
        __syncthreads();
    }

#pragma unroll
    for (int i = 0; i < 8; i++) {
        int rl = ty + 8 * i;
        if (m0 + rl < nrows) {
            size_t row = (size_t)srows[rl];
#pragma unroll
            for (int j = 0; j < 8; j++)
                g_T[row * 256 + tx + 32 * j] = acc[i][j];
        }
    }
}

// ===========================================================================
// Fixup epilogue: exact recompute of flagged rows, overwrite outputs.
// ===========================================================================
__global__ __launch_bounds__(256)
void k_fixEpi(const float* __restrict__ h, const int* __restrict__ prev_sel,
              const float* __restrict__ tau, const float* __restrict__ Wg,
              const float* __restrict__ bg, float* __restrict__ out, int B)
{
    __shared__ float sH[RDIM];
    __shared__ float sPart[4][EDIM];
    __shared__ float sL[EDIM];
    const int j = threadIdx.x;
    const int n = g_cnt;

    for (int r = blockIdx.x; r < n; r += gridDim.x) {
        size_t row = (size_t)g_rows[r];
        float hj = h[row * 256 + j];
        float Tj = g_T[row * 256 + j];
        sH[j] = hj + 0.1f * (-hj / tau[j] + tanhf(Tj + g_c[j]));
        __syncthreads();

        int e = j & 63, p = j >> 6;
        float acc = 0.f;
#pragma unroll 8
        for (int k = p * 64; k < p * 64 + 64; k++)
            acc = fmaf(sH[k], Wg[k * EDIM + e], acc);
        sPart[p][e] = acc;
        __syncthreads();

        if (j < EDIM) {
            float lg = sPart[0][j] + sPart[1][j] + sPart[2][j] + sPart[3][j] + bg[j];
            int p0 = prev_sel[row * 2 + 0];
            int p1 = prev_sel[row * 2 + 1];
            if (j == p0 || j == p1) lg += 0.1f;
            sL[j] = lg;
        }
        __syncthreads();

        if (j == 0) {
            float v1 = -1e30f, v2 = -1e30f;
            int i1 = 0, i2 = 0;
#pragma unroll
            for (int q = 0; q < 64; q++) {
                float v = sL[q];
                if (v > v1) { v2 = v1; i2 = i1; v1 = v; i1 = q; }
                else if (v > v2) { v2 = v; i2 = q; }
            }
            float e2 = expf(v2 - v1);
            float sm = 1.f + e2;
            out[row * 2 + 0] = (float)i1;
            out[row * 2 + 1] = (float)i2;
            size_t woff = (size_t)2 * B;
            out[woff + row * 2 + 0] = 1.f / sm;
            out[woff + row * 2 + 1] = e2 / sm;
        }
        __syncthreads();
    }
}

// ===========================================================================
extern "C" void kernel_launch(void* const* d_in, const int* in_sizes, int n_in,
                              void* d_out, int out_size)
{
    const float *x = 0, *h = 0, *Wp = 0, *bp = 0, *tau = 0, *A = 0, *Bm = 0,
                *Wg = 0, *bg = 0;
    const int* prev_sel = 0;
    for (int i = 0; i < n_in; i++) {
        int s = in_sizes[i];
        const void* pv = d_in[i];
        switch (s) {
            case BATCH * HID:  x = (const float*)pv; break;
            case BATCH * RDIM: h = (const float*)pv; break;
            case BATCH * TOPK: prev_sel = (const int*)pv; break;
            case HID * RDIM:   Wp = (const float*)pv; break;
            case RDIM:         if (!bp) bp = (const float*)pv; else tau = (const float*)pv; break;
            case RDIM * RDIM:  if (!A) A = (const float*)pv; else Bm = (const float*)pv; break;
            case RDIM * EDIM:  Wg = (const float*)pv; break;
            case EDIM:         bg = (const float*)pv; break;
            default: break;
        }
    }
    if (!x)        x        = (const float*)d_in[0];
    if (!h)        h        = (const float*)d_in[1];
    if (!prev_sel) prev_sel = (const int*)d_in[2];
    if (!Wp)       Wp       = (const float*)d_in[3];
    if (!bp)       bp       = (const float*)d_in[4];
    if (!tau)      tau      = (const float*)d_in[5];
    if (!A)        A        = (const float*)d_in[6];
    if (!Bm)       Bm       = (const float*)d_in[7];
    if (!Wg)       Wg       = (const float*)d_in[8];
    if (!bg)       bg       = (const float*)d_in[9];

    static int attr_done = 0;
    if (!attr_done) {
        cudaFuncSetAttribute(gemm_fused, cudaFuncAttributeMaxDynamicSharedMemorySize, SMEM_GEMM);
        cudaFuncSetAttribute(k_epi, cudaFuncAttributeMaxDynamicSharedMemorySize, SMEM_EPI);
        attr_done = 1;
    }

    float *Wptr = 0, *Tp = 0;
    cudaGetSymbolAddress((void**)&Wptr, g_W);
    cudaGetSymbolAddress((void**)&Tp, g_T);
    float* out = (float*)d_out;

    // 1) g_W = [A ; Wp@Bm], g_c = bp@Bm, g_cnt = 0
    k_prep<<<HID, 256>>>(Wp, Bm, A, bp);
    // 2) T = [h | x] @ g_W   (single-pass tf32)
    dim3 grid(BATCH / 128, 2);
    gemm_fused<<<grid, 256, SMEM_GEMM>>>(h, x, Wptr, Tp);
    // 3) epilogue + ambiguity flagging
    k_epi<<<BATCH / EROWS, 256, SMEM_EPI>>>(h, prev_sel, tau, Wg, bg, out, BATCH);
    // 4) exact fp32 recompute of flagged rows
    k_fixT<<<BATCH / 64, 256>>>(h, x, Wptr);
    k_fixEpi<<<2048, 256>>>(h, prev_sel, tau, Wg, bg, out, BATCH);
}

// round 8
// speedup vs baseline: 2.9649x; 1.4221x over previous
#include <cuda_runtime.h>
#include <cstdint>

#define BATCH 65536
#define HID   4096
#define RDIM  256
#define EDIM  64
#define TOPK  2
#define KTOT  (RDIM + HID)        // 4352
#define NS    (KTOT / 32)         // 136 stages
#define THR   2e-3f               // ambiguity threshold on logit gaps
#define MAXFIX 8192               // max rows recomputed exactly
#define KSPL  16                  // K splits in fixup
#define KCHUNK (KTOT / KSPL)      // 272

// ---------------- device scratch ----------------
__device__ float g_W[(size_t)KTOT * RDIM];   // [A ; Wp@Bm] stacked, [K][256]
__device__ float g_c[RDIM];                  // bp @ Bm
__device__ float g_T[(size_t)BATCH * RDIM];  // tf32 h@A + x@Wf
__device__ int   g_cnt;                      // # ambiguous rows
__device__ int   g_rows[BATCH];              // ambiguous row ids
__device__ float g_part[(size_t)MAXFIX * KSPL * RDIM];  // fixup partials (128MB)

// ---------------- helpers ----------------
__device__ __forceinline__ uint32_t smem_u32(const void* p) {
    uint32_t a;
    asm("{ .reg .u64 t; cvta.to.shared.u64 t, %1; cvt.u32.u64 %0, t; }"
        : "=r"(a) : "l"(p));
    return a;
}
__device__ __forceinline__ uint32_t to_tf32(float v) {
    uint32_t u;
    asm("cvt.rna.tf32.f32 %0, %1;" : "=r"(u) : "f"(v));
    return u;
}
__device__ __forceinline__ void mma_tf32(float d[4],
                                         const uint32_t a[4],
                                         uint32_t b0, uint32_t b1) {
    asm volatile(
        "mma.sync.aligned.m16n8k8.row.col.f32.tf32.tf32.f32 "
        "{%0,%1,%2,%3}, {%4,%5,%6,%7}, {%8,%9}, {%0,%1,%2,%3};"
        : "+f"(d[0]), "+f"(d[1]), "+f"(d[2]), "+f"(d[3])
        : "r"(a[0]), "r"(a[1]), "r"(a[2]), "r"(a[3]), "r"(b0), "r"(b1));
}
#define CP_ASYNC16(dst, src) \
    asm volatile("cp.async.cg.shared.global [%0], [%1], 16;" :: "r"(dst), "l"(src))
#define CP_COMMIT() asm volatile("cp.async.commit_group;" ::: "memory")
#define CP_WAIT1()  asm volatile("cp.async.wait_group 1;" ::: "memory")

// ---------------- GEMM smem layout ----------------
#define A_ST 36
#define B_ST 136
#define ABUF (128 * A_ST * 4)         // 18432 B
#define BBUF (32 * B_ST * 4)          // 17408 B
#define OFF_A(b) ((b) * ABUF)
#define OFF_B(b) (3 * ABUF + (b) * BBUF)
#define SMEM_GEMM (3 * ABUF + 3 * BBUF)   // 107520 B -> 2 CTAs/SM

// ===========================================================================
// Single-pass TF32 GEMM: T[B,256] = [h | x] @ W[4352,256]
// CTA 128(M) x 128(N), BK=32, 256 threads, warp tile 64x32,
// 3-stage cp.async ring, 2 CTAs/SM.
// ===========================================================================
__global__ __launch_bounds__(256, 2)
void gemm_fused(const float* __restrict__ Xh, const float* __restrict__ Xx,
                const float* __restrict__ W, float* __restrict__ C)
{
    extern __shared__ __align__(128) char smem[];
    const uint32_t sb = smem_u32(smem);

    const int tid  = threadIdx.x;
    const int warp = tid >> 5;
    const int lane = tid & 31;
    const int g    = lane >> 2;
    const int tg   = lane & 3;
    const int wm   = (warp >> 2) * 64;
    const int wn   = (warp & 3) * 32;
    const int m0   = blockIdx.x * 128;
    const int n0   = blockIdx.y * 128;

    float d[4][4][4];
#pragma unroll
    for (int mt = 0; mt < 4; mt++)
#pragma unroll
        for (int nt = 0; nt < 4; nt++)
#pragma unroll
            for (int q = 0; q < 4; q++) d[mt][nt][q] = 0.f;

    auto issue = [&](int s) {
        const int k0  = s * 32;
        const int buf = s % 3;
        uint32_t abase = sb + OFF_A(buf);
#pragma unroll
        for (int i = 0; i < 4; i++) {
            int lin = i * 256 + tid;
            int row = lin >> 3;
            int c4  = lin & 7;
            int kg  = k0 + c4 * 4;
            const float* src = (kg < RDIM)
                ? (Xh + (size_t)(m0 + row) * RDIM + kg)
                : (Xx + (size_t)(m0 + row) * HID + (kg - RDIM));
            CP_ASYNC16(abase + (uint32_t)(row * A_ST + c4 * 4) * 4, src);
        }
        uint32_t bbase = sb + OFF_B(buf);
#pragma unroll
        for (int i = 0; i < 4; i++) {
            int lin = i * 256 + tid;
            int kr  = lin >> 5;
            int c16 = lin & 31;
            CP_ASYNC16(bbase + (uint32_t)(kr * B_ST + c16 * 4) * 4,
                       W + (size_t)(k0 + kr) * 256 + n0 + c16 * 4);
        }
        CP_COMMIT();
    };

    auto compute = [&](int buf) {
        const float* As = (const float*)(smem + OFF_A(buf));
        const float* Bs = (const float*)(smem + OFF_B(buf));
#pragma unroll
        for (int k8 = 0; k8 < 4; k8++) {
            const int kk = k8 * 8;
            uint32_t bh[4][2];
#pragma unroll
            for (int nt = 0; nt < 4; nt++) {
                int nb = wn + nt * 8 + g;
                bh[nt][0] = to_tf32(Bs[(kk + tg) * B_ST + nb]);
                bh[nt][1] = to_tf32(Bs[(kk + tg + 4) * B_ST + nb]);
            }
#pragma unroll
            for (int mh = 0; mh < 2; mh++) {
                uint32_t fah[2][4];
#pragma unroll
                for (int mi = 0; mi < 2; mi++) {
                    int mt = mh * 2 + mi;
                    int base = (wm + mt * 16 + g) * A_ST + kk + tg;
                    fah[mi][0] = to_tf32(As[base]);
                    fah[mi][1] = to_tf32(As[base + 8 * A_ST]);
                    fah[mi][2] = to_tf32(As[base + 4]);
                    fah[mi][3] = to_tf32(As[base + 8 * A_ST + 4]);
                }
#pragma unroll
                for (int nt = 0; nt < 4; nt++)
#pragma unroll
                    for (int mi = 0; mi < 2; mi++)
                        mma_tf32(d[mh * 2 + mi][nt], fah[mi], bh[nt][0], bh[nt][1]);
            }
        }
    };

    issue(0);
    issue(1);
    for (int s = 0; s < NS; s++) {
        CP_WAIT1();
        __syncthreads();
        if (s + 2 < NS) issue(s + 2); else CP_COMMIT();
        compute(s % 3);
    }

#pragma unroll
    for (int mt = 0; mt < 4; mt++) {
        int r0 = m0 + wm + mt * 16 + g;
#pragma unroll
        for (int nt = 0; nt < 4; nt++) {
            int c0 = n0 + wn + nt * 8 + tg * 2;
            *reinterpret_cast<float2*>(C + (size_t)r0 * 256 + c0) =
                make_float2(d[mt][nt][0], d[mt][nt][1]);
            *reinterpret_cast<float2*>(C + (size_t)(r0 + 8) * 256 + c0) =
                make_float2(d[mt][nt][2], d[mt][nt][3]);
        }
    }
}

// ===========================================================================
// Prep: g_W = [A ; Wp@Bm], g_c = bp@Bm, g_cnt = 0.
// 16 Wp rows per block, grid = HID/16 = 256.
// ===========================================================================
__global__ __launch_bounds__(256)
void k_prep(const float* __restrict__ Wp, const float* __restrict__ Bm,
            const float* __restrict__ A, const float* __restrict__ bp)
{
    __shared__ float sW16[16][257];
    const int tid = threadIdx.x;
    const int i0 = blockIdx.x * 16;
    if (blockIdx.x == 0 && tid == 0) g_cnt = 0;

#pragma unroll
    for (int r = 0; r < 16; r++)
        sW16[r][tid] = Wp[(size_t)(i0 + r) * RDIM + tid];
    __syncthreads();

    float acc[16];
#pragma unroll
    for (int r = 0; r < 16; r++) acc[r] = 0.f;
#pragma unroll 4
    for (int k = 0; k < RDIM; k++) {
        float bmv = Bm[k * RDIM + tid];
#pragma unroll
        for (int r = 0; r < 16; r++)
            acc[r] = fmaf(sW16[r][k], bmv, acc[r]);
    }
#pragma unroll
    for (int r = 0; r < 16; r++)
        g_W[(size_t)(RDIM + i0 + r) * RDIM + tid] = acc[r];

    if (i0 < RDIM) {
#pragma unroll
        for (int r = 0; r < 16; r++)
            g_W[(size_t)(i0 + r) * RDIM + tid] = A[(size_t)(i0 + r) * RDIM + tid];
    }
    if (blockIdx.x == 0) {
        float c = 0.f;
#pragma unroll 4
        for (int k = 0; k < RDIM; k++)
            c = fmaf(bp[k], Bm[k * RDIM + tid], c);
        g_c[tid] = c;
    }
}

// ===========================================================================
// Epilogue: 32 rows/block; flags ambiguous rows (gap12 or gap23 < THR).
// Wg kept k-major in smem [256][68]; thread = 4 experts x 2 rows.
// Logit accumulation order (k ascending per output) identical to prior round.
// ===========================================================================
#define EROWS   32
#define WG_ST2  68
#define H_ST    260
#define SMEM_EPI (256 * WG_ST2 * 4 + EROWS * H_ST * 4 + EROWS * 64 * 4)  // 111104
__global__ __launch_bounds__(256)
void k_epi(const float* __restrict__ h, const int* __restrict__ prev_sel,
           const float* __restrict__ tau, const float* __restrict__ Wg,
           const float* __restrict__ bg, float* __restrict__ out, int B)
{
    extern __shared__ __align__(16) char esm[];
    float* sWg = (float*)esm;                               // [256][68] k-major
    float* sH  = (float*)(esm + 256 * WG_ST2 * 4);          // [32][260]
    float* sL  = (float*)(esm + 256 * WG_ST2 * 4 + EROWS * H_ST * 4); // [32][64]
    const int tid = threadIdx.x;
    const size_t r0 = (size_t)blockIdx.x * EROWS;

    // Wg: direct copy, k-major rows of 64 (+4 pad)
#pragma unroll
    for (int i = 0; i < 16; i++) {
        int f = i * 256 + tid;           // 0..4095
        int k = f >> 4;                  // 0..255
        int e4 = (f & 15) * 4;           // float4 col
        *reinterpret_cast<float4*>(&sWg[k * WG_ST2 + e4]) =
            *reinterpret_cast<const float4*>(Wg + k * 64 + e4);
    }
    // tanh update: thread owns column tid across 32 rows
    {
        float tauv = tau[tid];
        float cv   = g_c[tid];
#pragma unroll
        for (int row = 0; row < EROWS; row++) {
            size_t gidx = (r0 + row) * 256 + tid;
            float hj = h[gidx];
            float Tj = g_T[gidx];
            sH[row * H_ST + tid] = hj + 0.1f * (-hj / tauv + tanhf(Tj + cv));
        }
    }
    __syncthreads();

    // logits: thread -> 4 experts (eg..eg+3) x 2 rows (rb, rb+16)
    {
        const int eg = (tid & 15) * 4;
        const int rb = tid >> 4;
        float4 acc0 = make_float4(0.f, 0.f, 0.f, 0.f);
        float4 acc1 = make_float4(0.f, 0.f, 0.f, 0.f);
        const float* h0 = sH + rb * H_ST;
        const float* h1 = sH + (rb + 16) * H_ST;
#pragma unroll 8
        for (int k = 0; k < RDIM; k++) {
            float4 w = *reinterpret_cast<const float4*>(&sWg[k * WG_ST2 + eg]);
            float a = h0[k], b = h1[k];
            acc0.x = fmaf(a, w.x, acc0.x); acc0.y = fmaf(a, w.y, acc0.y);
            acc0.z = fmaf(a, w.z, acc0.z); acc0.w = fmaf(a, w.w, acc0.w);
            acc1.x = fmaf(b, w.x, acc1.x); acc1.y = fmaf(b, w.y, acc1.y);
            acc1.z = fmaf(b, w.z, acc1.z); acc1.w = fmaf(b, w.w, acc1.w);
        }
        float4 bgv = *reinterpret_cast<const float4*>(bg + eg);
        acc0.x += bgv.x; acc0.y += bgv.y; acc0.z += bgv.z; acc0.w += bgv.w;
        acc1.x += bgv.x; acc1.y += bgv.y; acc1.z += bgv.z; acc1.w += bgv.w;
        *reinterpret_cast<float4*>(&sL[rb * 64 + eg]) = acc0;
        *reinterpret_cast<float4*>(&sL[(rb + 16) * 64 + eg]) = acc1;
    }
    __syncthreads();

    if (tid < EROWS) {
        int row = tid;
        size_t orow = r0 + row;
        int p0 = prev_sel[orow * 2 + 0];
        int p1 = prev_sel[orow * 2 + 1];
        float v1 = -1e30f, v2 = -1e30f, v3 = -1e30f;
        int i1 = 0, i2 = 0;
#pragma unroll
        for (int q = 0; q < 64; q++) {
            float v = sL[row * 64 + q] + ((q == p0 || q == p1) ? 0.1f : 0.f);
            if (v > v1)      { v3 = v2; v2 = v1; i2 = i1; v1 = v; i1 = q; }
            else if (v > v2) { v3 = v2; v2 = v; i2 = q; }
            else if (v > v3) { v3 = v; }
        }
        float gap = fminf(v1 - v2, v2 - v3);
        if (gap < THR) {
            int slot = atomicAdd(&g_cnt, 1);
            if (slot < BATCH) g_rows[slot] = (int)orow;
        }
        float e2 = expf(v2 - v1);
        float sm = 1.f + e2;
        out[orow * 2 + 0] = (float)i1;
        out[orow * 2 + 1] = (float)i2;
        size_t woff = (size_t)2 * B;
        out[woff + orow * 2 + 0] = 1.f / sm;
        out[woff + orow * 2 + 1] = e2 / sm;
    }
}

// ===========================================================================
// Fixup GEMM, split-K: grid (MAXFIX/64, KSPL). Each block computes a
// [64 rows x 256] partial over K-chunk KCHUNK into g_part (deterministic).
// ===========================================================================
__global__ __launch_bounds__(256)
void k_fixT(const float* __restrict__ h, const float* __restrict__ x,
            const float* __restrict__ W)
{
    int nrows = g_cnt; if (nrows > MAXFIX) nrows = MAXFIX;
    const int m0 = blockIdx.x * 64;
    if (m0 >= nrows) return;
    const int ks = blockIdx.y;
    const int kbase = ks * KCHUNK;

    __shared__ float sX[64][16];
    __shared__ float sW[16][256];
    __shared__ int   srows[64];

    const int tid = threadIdx.x;
    const int tx = tid & 31, ty = tid >> 5;
    const int xr = tid >> 2, xq = tid & 3;
    const int wr = tid >> 6, wc = tid & 63;

    if (tid < 64) {
        int idx = m0 + tid;
        srows[tid] = g_rows[idx < nrows ? idx : nrows - 1];
    }
    __syncthreads();

    float acc[8][8];
#pragma unroll
    for (int i = 0; i < 8; i++)
#pragma unroll
        for (int j = 0; j < 8; j++) acc[i][j] = 0.f;

    for (int k0 = kbase; k0 < kbase + KCHUNK; k0 += 16) {
        {
            int row = srows[xr];
            int kg = k0 + xq * 4;
            const float* src = (kg < RDIM)
                ? (h + (size_t)row * RDIM + kg)
                : (x + (size_t)row * HID + (kg - RDIM));
            *reinterpret_cast<float4*>(&sX[xr][xq * 4]) =
                *reinterpret_cast<const float4*>(src);
        }
#pragma unroll
        for (int r = 0; r < 4; r++)
            *reinterpret_cast<float4*>(&sW[wr + 4 * r][wc * 4]) =
                *reinterpret_cast<const float4*>(W + (size_t)(k0 + wr + 4 * r) * 256 + wc * 4);
        __syncthreads();

#pragma unroll
        for (int k = 0; k < 16; k++) {
            float a[8], b[8];
#pragma unroll
            for (int i = 0; i < 8; i++) a[i] = sX[ty + 8 * i][k];
#pragma unroll
            for (int j = 0; j < 8; j++) b[j] = sW[k][tx + 32 * j];
#pragma unroll
            for (int i = 0; i < 8; i++)
#pragma unroll
                for (int j = 0; j < 8; j++)
                    acc[i][j] = fmaf(a[i], b[j], acc[i][j]);
        }
        __syncthreads();
    }

#pragma unroll
    for (int i = 0; i < 8; i++) {
        int rl = ty + 8 * i;
        if (m0 + rl < nrows) {
            float* dst = &g_part[((size_t)(m0 + rl) * KSPL + ks) * RDIM];
#pragma unroll
            for (int j = 0; j < 8; j++)
                dst[tx + 32 * j] = acc[i][j];
        }
    }
}

// ===========================================================================
// Fixup epilogue: reduce K-split partials, exact recompute, overwrite.
// ===========================================================================
__global__ __launch_bounds__(256)
void k_fixEpi(const float* __restrict__ h, const int* __restrict__ prev_sel,
              const float* __restrict__ tau, const float* __restrict__ Wg,
              const float* __restrict__ bg, float* __restrict__ out, int B)
{
    __shared__ float sH[RDIM];
    __shared__ float sPart[4][EDIM];
    __shared__ float sL[EDIM];
    const int j = threadIdx.x;
    int n = g_cnt; if (n > MAXFIX) n = MAXFIX;

    for (int r = blockIdx.x; r < n; r += gridDim.x) {
        size_t row = (size_t)g_rows[r];
        float Tj = 0.f;
#pragma unroll
        for (int ks = 0; ks < KSPL; ks++)
            Tj += g_part[((size_t)r * KSPL + ks) * RDIM + j];
        float hj = h[row * 256 + j];
        sH[j] = hj + 0.1f * (-hj / tau[j] + tanhf(Tj + g_c[j]));
        __syncthreads();

        int e = j & 63, p = j >> 6;
        float acc = 0.f;
#pragma unroll 8
        for (int k = p * 64; k < p * 64 + 64; k++)
            acc = fmaf(sH[k], Wg[k * EDIM + e], acc);
        sPart[p][e] = acc;
        __syncthreads();

        if (j < EDIM) {
            float lg = sPart[0][j] + sPart[1][j] + sPart[2][j] + sPart[3][j] + bg[j];
            int p0 = prev_sel[row * 2 + 0];
            int p1 = prev_sel[row * 2 + 1];
            if (j == p0 || j == p1) lg += 0.1f;
            sL[j] = lg;
        }
        __syncthreads();

        if (j == 0) {
            float v1 = -1e30f, v2 = -1e30f;
            int i1 = 0, i2 = 0;
#pragma unroll
            for (int q = 0; q < 64; q++) {
                float v = sL[q];
                if (v > v1) { v2 = v1; i2 = i1; v1 = v; i1 = q; }
                else if (v > v2) { v2 = v; i2 = q; }
            }
            float e2 = expf(v2 - v1);
            float sm = 1.f + e2;
            out[row * 2 + 0] = (float)i1;
            out[row * 2 + 1] = (float)i2;
            size_t woff = (size_t)2 * B;
            out[woff + row * 2 + 0] = 1.f / sm;
            out[woff + row * 2 + 1] = e2 / sm;
        }
        __syncthreads();
    }
}

// ===========================================================================
extern "C" void kernel_launch(void* const* d_in, const int* in_sizes, int n_in,
                              void* d_out, int out_size)
{
    const float *x = 0, *h = 0, *Wp = 0, *bp = 0, *tau = 0, *A = 0, *Bm = 0,
                *Wg = 0, *bg = 0;
    const int* prev_sel = 0;
    for (int i = 0; i < n_in; i++) {
        int s = in_sizes[i];
        const void* pv = d_in[i];
        switch (s) {
            case BATCH * HID:  x = (const float*)pv; break;
            case BATCH * RDIM: h = (const float*)pv; break;
            case BATCH * TOPK: prev_sel = (const int*)pv; break;
            case HID * RDIM:   Wp = (const float*)pv; break;
            case RDIM:         if (!bp) bp = (const float*)pv; else tau = (const float*)pv; break;
            case RDIM * RDIM:  if (!A) A = (const float*)pv; else Bm = (const float*)pv; break;
            case RDIM * EDIM:  Wg = (const float*)pv; break;
            case EDIM:         bg = (const float*)pv; break;
            default: break;
        }
    }
    if (!x)        x        = (const float*)d_in[0];
    if (!h)        h        = (const float*)d_in[1];
    if (!prev_sel) prev_sel = (const int*)d_in[2];
    if (!Wp)       Wp       = (const float*)d_in[3];
    if (!bp)       bp       = (const float*)d_in[4];
    if (!tau)      tau      = (const float*)d_in[5];
    if (!A)        A        = (const float*)d_in[6];
    if (!Bm)       Bm       = (const float*)d_in[7];
    if (!Wg)       Wg       = (const float*)d_in[8];
    if (!bg)       bg       = (const float*)d_in[9];

    static int attr_done = 0;
    if (!attr_done) {
        cudaFuncSetAttribute(gemm_fused, cudaFuncAttributeMaxDynamicSharedMemorySize, SMEM_GEMM);
        cudaFuncSetAttribute(k_epi, cudaFuncAttributeMaxDynamicSharedMemorySize, SMEM_EPI);
        attr_done = 1;
    }

    float *Wptr = 0, *Tp = 0;
    cudaGetSymbolAddress((void**)&Wptr, g_W);
    cudaGetSymbolAddress((void**)&Tp, g_T);
    float* out = (float*)d_out;

    // 1) g_W = [A ; Wp@Bm], g_c = bp@Bm, g_cnt = 0
    k_prep<<<HID / 16, 256>>>(Wp, Bm, A, bp);
    // 2) T = [h | x] @ g_W   (single-pass tf32)
    dim3 grid(BATCH / 128, 2);
    gemm_fused<<<grid, 256, SMEM_GEMM>>>(h, x, Wptr, Tp);
    // 3) epilogue + ambiguity flagging
    k_epi<<<BATCH / EROWS, 256, SMEM_EPI>>>(h, prev_sel, tau, Wg, bg, out, BATCH);
    // 4) exact fp32 recompute of flagged rows (split-K, deterministic reduce)
    dim3 fgrid(MAXFIX / 64, KSPL);
    k_fixT<<<fgrid, 256>>>(h, x, Wptr);
    k_fixEpi<<<2048, 256>>>(h, prev_sel, tau, Wg, bg, out, BATCH);
}

// round 9
// speedup vs baseline: 3.3000x; 1.1130x over previous
#include <cuda_runtime.h>
#include <cuda_fp16.h>
#include <cstdint>

#define BATCH 65536
#define HID   4096
#define RDIM  256
#define EDIM  64
#define TOPK  2
#define KTOT  (RDIM + HID)        // 4352
#define NS    (KTOT / 32)         // 136 stages
#define THR   2e-3f               // ambiguity threshold on logit gaps
#define MAXFIX 8192               // max rows recomputed exactly
#define KSPL  16                  // K splits in fixup
#define KCHUNK (KTOT / KSPL)      // 272

// ---------------- device scratch ----------------
__device__ float  g_W[(size_t)KTOT * RDIM];    // fp32 [K][256] (fixup)
__device__ __half g_Wth[(size_t)RDIM * KTOT];  // fp16 [N][K] n-major (main GEMM)
__device__ float  g_c[RDIM];                   // bp @ Bm
__device__ float  g_T[(size_t)BATCH * RDIM];   // fp16-mma h@A + x@Wf
__device__ int    g_cnt;
__device__ int    g_rows[BATCH];
__device__ float  g_part[(size_t)MAXFIX * KSPL * RDIM];

// ---------------- helpers ----------------
__device__ __forceinline__ uint32_t smem_u32(const void* p) {
    uint32_t a;
    asm("{ .reg .u64 t; cvta.to.shared.u64 t, %1; cvt.u32.u64 %0, t; }"
        : "=r"(a) : "l"(p));
    return a;
}
__device__ __forceinline__ uint32_t pack_h2(float lo, float hi) {
    uint32_t r;  // first source -> upper half, second -> lower half
    asm("cvt.rn.f16x2.f32 %0, %1, %2;" : "=r"(r) : "f"(hi), "f"(lo));
    return r;
}
__device__ __forceinline__ void mma_f16(float d[4],
                                        uint32_t a0, uint32_t a1, uint32_t a2, uint32_t a3,
                                        uint32_t b0, uint32_t b1) {
    asm volatile(
        "mma.sync.aligned.m16n8k16.row.col.f32.f16.f16.f32 "
        "{%0,%1,%2,%3}, {%4,%5,%6,%7}, {%8,%9}, {%0,%1,%2,%3};"
        : "+f"(d[0]), "+f"(d[1]), "+f"(d[2]), "+f"(d[3])
        : "r"(a0), "r"(a1), "r"(a2), "r"(a3), "r"(b0), "r"(b1));
}
#define CP_ASYNC16(dst, src) \
    asm volatile("cp.async.cg.shared.global [%0], [%1], 16;" :: "r"(dst), "l"(src))
#define CP_COMMIT() asm volatile("cp.async.commit_group;" ::: "memory")
#define CP_WAIT1()  asm volatile("cp.async.wait_group 1;" ::: "memory")

// ---------------- GEMM smem layout ----------------
#define A_ST 36                        // A row stride (floats)
#define B_STH 40                       // B row stride (halfs) -> 80B, 16B-aligned
#define ABUF (128 * A_ST * 4)          // 18432 B
#define BBUF (128 * B_STH * 2)         // 10240 B
#define OFF_A(b) ((b) * ABUF)
#define OFF_B(b) (3 * ABUF + (b) * BBUF)
#define SMEM_GEMM (3 * ABUF + 3 * BBUF)   // 86016 B -> 2 CTAs/SM

// ===========================================================================
// Single-pass FP16 GEMM: T[B,256] = [h | x] @ W[4352,256]
// CTA 128(M) x 128(N), BK=32, 256 threads, warp tile 64x32,
// mma.m16n8k16.f16 (fp32 accum), 3-stage cp.async ring, 2 CTAs/SM.
// A: fp32 smem -> cvt.rn.f16x2 in registers. B: fp16 n-major smem, no cvt.
// ===========================================================================
__global__ __launch_bounds__(256, 2)
void gemm_fused(const float* __restrict__ Xh, const float* __restrict__ Xx,
                const __half* __restrict__ Wt, float* __restrict__ C)
{
    extern __shared__ __align__(128) char smem[];
    const uint32_t sb = smem_u32(smem);

    const int tid  = threadIdx.x;
    const int warp = tid >> 5;
    const int lane = tid & 31;
    const int g    = lane >> 2;
    const int tg   = lane & 3;
    const int wm   = (warp >> 2) * 64;
    const int wn   = (warp & 3) * 32;
    const int m0   = blockIdx.x * 128;
    const int n0   = blockIdx.y * 128;

    float d[4][4][4];
#pragma unroll
    for (int mt = 0; mt < 4; mt++)
#pragma unroll
        for (int nt = 0; nt < 4; nt++)
#pragma unroll
            for (int q = 0; q < 4; q++) d[mt][nt][q] = 0.f;

    auto issue = [&](int s) {
        const int k0  = s * 32;
        const int buf = s % 3;
        uint32_t abase = sb + OFF_A(buf);
#pragma unroll
        for (int i = 0; i < 4; i++) {
            int lin = i * 256 + tid;
            int row = lin >> 3;
            int c4  = lin & 7;
            int kg  = k0 + c4 * 4;
            const float* src = (kg < RDIM)
                ? (Xh + (size_t)(m0 + row) * RDIM + kg)
                : (Xx + (size_t)(m0 + row) * HID + (kg - RDIM));
            CP_ASYNC16(abase + (uint32_t)(row * A_ST + c4 * 4) * 4, src);
        }
        uint32_t bbase = sb + OFF_B(buf);
#pragma unroll
        for (int i = 0; i < 2; i++) {
            int lin = i * 256 + tid;          // 0..511
            int nr  = lin >> 2;               // 0..127 (n row)
            int c8  = lin & 3;                // 0..3 (8-half chunks)
            CP_ASYNC16(bbase + (uint32_t)(nr * B_STH + c8 * 8) * 2,
                       Wt + (size_t)(n0 + nr) * KTOT + k0 + c8 * 8);
        }
        CP_COMMIT();
    };

    auto compute = [&](int buf) {
        const float*  As = (const float*)(smem + OFF_A(buf));
        const __half* Bs = (const __half*)(smem + OFF_B(buf));
#pragma unroll
        for (int k16 = 0; k16 < 2; k16++) {
            const int kk = k16 * 16;
            // B fragments: direct u32 loads (fp16 pairs along k)
            uint32_t b0[4], b1[4];
#pragma unroll
            for (int nt = 0; nt < 4; nt++) {
                int nb = wn + nt * 8 + g;
                b0[nt] = *reinterpret_cast<const uint32_t*>(&Bs[nb * B_STH + kk + 2 * tg]);
                b1[nt] = *reinterpret_cast<const uint32_t*>(&Bs[nb * B_STH + kk + 2 * tg + 8]);
            }
            // A fragments: float2 loads + cvt
#pragma unroll
            for (int mt = 0; mt < 4; mt++) {
                int r = (wm + mt * 16 + g) * A_ST + kk + 2 * tg;
                float2 v0 = *reinterpret_cast<const float2*>(&As[r]);
                float2 v1 = *reinterpret_cast<const float2*>(&As[r + 8 * A_ST]);
                float2 v2 = *reinterpret_cast<const float2*>(&As[r + 8]);
                float2 v3 = *reinterpret_cast<const float2*>(&As[r + 8 * A_ST + 8]);
                uint32_t a0 = pack_h2(v0.x, v0.y);
                uint32_t a1 = pack_h2(v1.x, v1.y);
                uint32_t a2 = pack_h2(v2.x, v2.y);
                uint32_t a3 = pack_h2(v3.x, v3.y);
#pragma unroll
                for (int nt = 0; nt < 4; nt++)
                    mma_f16(d[mt][nt], a0, a1, a2, a3, b0[nt], b1[nt]);
            }
        }
    };

    issue(0);
    issue(1);
    for (int s = 0; s < NS; s++) {
        CP_WAIT1();
        __syncthreads();
        if (s + 2 < NS) issue(s + 2); else CP_COMMIT();
        compute(s % 3);
    }

#pragma unroll
    for (int mt = 0; mt < 4; mt++) {
        int r0 = m0 + wm + mt * 16 + g;
#pragma unroll
        for (int nt = 0; nt < 4; nt++) {
            int c0 = n0 + wn + nt * 8 + tg * 2;
            *reinterpret_cast<float2*>(C + (size_t)r0 * 256 + c0) =
                make_float2(d[mt][nt][0], d[mt][nt][1]);
            *reinterpret_cast<float2*>(C + (size_t)(r0 + 8) * 256 + c0) =
                make_float2(d[mt][nt][2], d[mt][nt][3]);
        }
    }
}

// ===========================================================================
// Prep: g_W(fp32 k-major) = [A ; Wp@Bm]; g_Wth(fp16 n-major) = same, transposed;
// g_c = bp@Bm; g_cnt = 0.  16 k-rows/block, grid = KTOT/16 = 272.
// Blocks 0..15 handle A rows, 16..271 handle Wp@Bm rows.
// ===========================================================================
__global__ __launch_bounds__(256)
void k_prep(const float* __restrict__ Wp, const float* __restrict__ Bm,
            const float* __restrict__ A, const float* __restrict__ bp)
{
    __shared__ float sW16[16][257];
    const int tid = threadIdx.x;
    const int kb = blockIdx.x * 16;       // global k base (0..4351)
    if (blockIdx.x == 0 && tid == 0) g_cnt = 0;

    float vals[16];
    if (kb < RDIM) {
        // A rows: copy
#pragma unroll
        for (int r = 0; r < 16; r++) {
            vals[r] = A[(size_t)(kb + r) * RDIM + tid];
            g_W[(size_t)(kb + r) * RDIM + tid] = vals[r];
        }
    } else {
        const int i0 = kb - RDIM;          // Wp row base
#pragma unroll
        for (int r = 0; r < 16; r++)
            sW16[r][tid] = Wp[(size_t)(i0 + r) * RDIM + tid];
        __syncthreads();
#pragma unroll
        for (int r = 0; r < 16; r++) vals[r] = 0.f;
#pragma unroll 4
        for (int k = 0; k < RDIM; k++) {
            float bmv = Bm[k * RDIM + tid];
#pragma unroll
            for (int r = 0; r < 16; r++)
                vals[r] = fmaf(sW16[r][k], bmv, vals[r]);
        }
#pragma unroll
        for (int r = 0; r < 16; r++)
            g_W[(size_t)(kb + r) * RDIM + tid] = vals[r];
    }

    // fp16 transposed write: thread tid owns column n = tid; 16 contiguous k.
    {
        uint32_t p[8];
#pragma unroll
        for (int j = 0; j < 8; j++) {
            uint32_t r;
            asm("cvt.rn.f16x2.f32 %0, %1, %2;" : "=r"(r)
                : "f"(vals[2 * j + 1]), "f"(vals[2 * j]));
            p[j] = r;
        }
        uint4* dst = reinterpret_cast<uint4*>(
            reinterpret_cast<char*>(g_Wth) + ((size_t)tid * KTOT + kb) * 2);
        dst[0] = make_uint4(p[0], p[1], p[2], p[3]);
        dst[1] = make_uint4(p[4], p[5], p[6], p[7]);
    }

    if (blockIdx.x == 0) {
        float c = 0.f;
#pragma unroll 4
        for (int k = 0; k < RDIM; k++)
            c = fmaf(bp[k], Bm[k * RDIM + tid], c);
        g_c[tid] = c;
    }
}

// ===========================================================================
// Epilogue: 32 rows/block; flags ambiguous rows (gap12 or gap23 < THR).
// ===========================================================================
#define EROWS   32
#define WG_ST2  68
#define H_ST    260
#define SMEM_EPI (256 * WG_ST2 * 4 + EROWS * H_ST * 4 + EROWS * 64 * 4)  // 111104
__global__ __launch_bounds__(256)
void k_epi(const float* __restrict__ h, const int* __restrict__ prev_sel,
           const float* __restrict__ tau, const float* __restrict__ Wg,
           const float* __restrict__ bg, float* __restrict__ out, int B)
{
    extern __shared__ __align__(16) char esm[];
    float* sWg = (float*)esm;                               // [256][68] k-major
    float* sH  = (float*)(esm + 256 * WG_ST2 * 4);          // [32][260]
    float* sL  = (float*)(esm + 256 * WG_ST2 * 4 + EROWS * H_ST * 4); // [32][64]
    const int tid = threadIdx.x;
    const size_t r0 = (size_t)blockIdx.x * EROWS;

#pragma unroll
    for (int i = 0; i < 16; i++) {
        int f = i * 256 + tid;
        int k = f >> 4;
        int e4 = (f & 15) * 4;
        *reinterpret_cast<float4*>(&sWg[k * WG_ST2 + e4]) =
            *reinterpret_cast<const float4*>(Wg + k * 64 + e4);
    }
    {
        float tauv = tau[tid];
        float cv   = g_c[tid];
#pragma unroll
        for (int row = 0; row < EROWS; row++) {
            size_t gidx = (r0 + row) * 256 + tid;
            float hj = h[gidx];
            float Tj = g_T[gidx];
            sH[row * H_ST + tid] = hj + 0.1f * (-hj / tauv + tanhf(Tj + cv));
        }
    }
    __syncthreads();

    {
        const int eg = (tid & 15) * 4;
        const int rb = tid >> 4;
        float4 acc0 = make_float4(0.f, 0.f, 0.f, 0.f);
        float4 acc1 = make_float4(0.f, 0.f, 0.f, 0.f);
        const float* h0 = sH + rb * H_ST;
        const float* h1 = sH + (rb + 16) * H_ST;
#pragma unroll 8
        for (int k = 0; k < RDIM; k++) {
            float4 w = *reinterpret_cast<const float4*>(&sWg[k * WG_ST2 + eg]);
            float a = h0[k], b = h1[k];
            acc0.x = fmaf(a, w.x, acc0.x); acc0.y = fmaf(a, w.y, acc0.y);
            acc0.z = fmaf(a, w.z, acc0.z); acc0.w = fmaf(a, w.w, acc0.w);
            acc1.x = fmaf(b, w.x, acc1.x); acc1.y = fmaf(b, w.y, acc1.y);
            acc1.z = fmaf(b, w.z, acc1.z); acc1.w = fmaf(b, w.w, acc1.w);
        }
        float4 bgv = *reinterpret_cast<const float4*>(bg + eg);
        acc0.x += bgv.x; acc0.y += bgv.y; acc0.z += bgv.z; acc0.w += bgv.w;
        acc1.x += bgv.x; acc1.y += bgv.y; acc1.z += bgv.z; acc1.w += bgv.w;
        *reinterpret_cast<float4*>(&sL[rb * 64 + eg]) = acc0;
        *reinterpret_cast<float4*>(&sL[(rb + 16) * 64 + eg]) = acc1;
    }
    __syncthreads();

    if (tid < EROWS) {
        int row = tid;
        size_t orow = r0 + row;
        int p0 = prev_sel[orow * 2 + 0];
        int p1 = prev_sel[orow * 2 + 1];
        float v1 = -1e30f, v2 = -1e30f, v3 = -1e30f;
        int i1 = 0, i2 = 0;
#pragma unroll
        for (int q = 0; q < 64; q++) {
            float v = sL[row * 64 + q] + ((q == p0 || q == p1) ? 0.1f : 0.f);
            if (v > v1)      { v3 = v2; v2 = v1; i2 = i1; v1 = v; i1 = q; }
            else if (v > v2) { v3 = v2; v2 = v; i2 = q; }
            else if (v > v3) { v3 = v; }
        }
        float gap = fminf(v1 - v2, v2 - v3);
        if (gap < THR) {
            int slot = atomicAdd(&g_cnt, 1);
            if (slot < BATCH) g_rows[slot] = (int)orow;
        }
        float e2 = expf(v2 - v1);
        float sm = 1.f + e2;
        out[orow * 2 + 0] = (float)i1;
        out[orow * 2 + 1] = (float)i2;
        size_t woff = (size_t)2 * B;
        out[woff + orow * 2 + 0] = 1.f / sm;
        out[woff + orow * 2 + 1] = e2 / sm;
    }
}

// ===========================================================================
// Fixup GEMM, split-K: grid (MAXFIX/64, KSPL), fp32 exact partials.
// ===========================================================================
__global__ __launch_bounds__(256)
void k_fixT(const float* __restrict__ h, const float* __restrict__ x,
            const float* __restrict__ W)
{
    int nrows = g_cnt; if (nrows > MAXFIX) nrows = MAXFIX;
    const int m0 = blockIdx.x * 64;
    if (m0 >= nrows) return;
    const int ks = blockIdx.y;
    const int kbase = ks * KCHUNK;

    __shared__ float sX[64][16];
    __shared__ float sW[16][256];
    __shared__ int   srows[64];

    const int tid = threadIdx.x;
    const int tx = tid & 31, ty = tid >> 5;
    const int xr = tid >> 2, xq = tid & 3;
    const int wr = tid >> 6, wc = tid & 63;

    if (tid < 64) {
        int idx = m0 + tid;
        srows[tid] = g_rows[idx < nrows ? idx : nrows - 1];
    }
    __syncthreads();

    float acc[8][8];
#pragma unroll
    for (int i = 0; i < 8; i++)
#pragma unroll
        for (int j = 0; j < 8; j++) acc[i][j] = 0.f;

    for (int k0 = kbase; k0 < kbase + KCHUNK; k0 += 16) {
        {
            int row = srows[xr];
            int kg = k0 + xq * 4;
            const float* src = (kg < RDIM)
                ? (h + (size_t)row * RDIM + kg)
                : (x + (size_t)row * HID + (kg - RDIM));
            *reinterpret_cast<float4*>(&sX[xr][xq * 4]) =
                *reinterpret_cast<const float4*>(src);
        }
#pragma unroll
        for (int r = 0; r < 4; r++)
            *reinterpret_cast<float4*>(&sW[wr + 4 * r][wc * 4]) =
                *reinterpret_cast<const float4*>(W + (size_t)(k0 + wr + 4 * r) * 256 + wc * 4);
        __syncthreads();

#pragma unroll
        for (int k = 0; k < 16; k++) {
            float a[8], b[8];
#pragma unroll
            for (int i = 0; i < 8; i++) a[i] = sX[ty + 8 * i][k];
#pragma unroll
            for (int j = 0; j < 8; j++) b[j] = sW[k][tx + 32 * j];
#pragma unroll
            for (int i = 0; i < 8; i++)
#pragma unroll
                for (int j = 0; j < 8; j++)
                    acc[i][j] = fmaf(a[i], b[j], acc[i][j]);
        }
        __syncthreads();
    }

#pragma unroll
    for (int i = 0; i < 8; i++) {
        int rl = ty + 8 * i;
        if (m0 + rl < nrows) {
            float* dst = &g_part[((size_t)(m0 + rl) * KSPL + ks) * RDIM];
#pragma unroll
            for (int j = 0; j < 8; j++)
                dst[tx + 32 * j] = acc[i][j];
        }
    }
}

// ===========================================================================
// Fixup epilogue: reduce K-split partials, exact recompute, overwrite.
// ===========================================================================
__global__ __launch_bounds__(256)
void k_fixEpi(const float* __restrict__ h, const int* __restrict__ prev_sel,
              const float* __restrict__ tau, const float* __restrict__ Wg,
              const float* __restrict__ bg, float* __restrict__ out, int B)
{
    __shared__ float sH[RDIM];
    __shared__ float sPart[4][EDIM];
    __shared__ float sL[EDIM];
    const int j = threadIdx.x;
    int n = g_cnt; if (n > MAXFIX) n = MAXFIX;

    for (int r = blockIdx.x; r < n; r += gridDim.x) {
        size_t row = (size_t)g_rows[r];
        float Tj = 0.f;
#pragma unroll
        for (int ks = 0; ks < KSPL; ks++)
            Tj += g_part[((size_t)r * KSPL + ks) * RDIM + j];
        float hj = h[row * 256 + j];
        sH[j] = hj + 0.1f * (-hj / tau[j] + tanhf(Tj + g_c[j]));
        __syncthreads();

        int e = j & 63, p = j >> 6;
        float acc = 0.f;
#pragma unroll 8
        for (int k = p * 64; k < p * 64 + 64; k++)
            acc = fmaf(sH[k], Wg[k * EDIM + e], acc);
        sPart[p][e] = acc;
        __syncthreads();

        if (j < EDIM) {
            float lg = sPart[0][j] + sPart[1][j] + sPart[2][j] + sPart[3][j] + bg[j];
            int p0 = prev_sel[row * 2 + 0];
            int p1 = prev_sel[row * 2 + 1];
            if (j == p0 || j == p1) lg += 0.1f;
            sL[j] = lg;
        }
        __syncthreads();

        if (j == 0) {
            float v1 = -1e30f, v2 = -1e30f;
            int i1 = 0, i2 = 0;
#pragma unroll
            for (int q = 0; q < 64; q++) {
                float v = sL[q];
                if (v > v1) { v2 = v1; i2 = i1; v1 = v; i1 = q; }
                else if (v > v2) { v2 = v; i2 = q; }
            }
            float e2 = expf(v2 - v1);
            float sm = 1.f + e2;
            out[row * 2 + 0] = (float)i1;
            out[row * 2 + 1] = (float)i2;
            size_t woff = (size_t)2 * B;
            out[woff + row * 2 + 0] = 1.f / sm;
            out[woff + row * 2 + 1] = e2 / sm;
        }
        __syncthreads();
    }
}

// ===========================================================================
extern "C" void kernel_launch(void* const* d_in, const int* in_sizes, int n_in,
                              void* d_out, int out_size)
{
    const float *x = 0, *h = 0, *Wp = 0, *bp = 0, *tau = 0, *A = 0, *Bm = 0,
                *Wg = 0, *bg = 0;
    const int* prev_sel = 0;
    for (int i = 0; i < n_in; i++) {
        int s = in_sizes[i];
        const void* pv = d_in[i];
        switch (s) {
            case BATCH * HID:  x = (const float*)pv; break;
            case BATCH * RDIM: h = (const float*)pv; break;
            case BATCH * TOPK: prev_sel = (const int*)pv; break;
            case HID * RDIM:   Wp = (const float*)pv; break;
            case RDIM:         if (!bp) bp = (const float*)pv; else tau = (const float*)pv; break;
            case RDIM * RDIM:  if (!A) A = (const float*)pv; else Bm = (const float*)pv; break;
            case RDIM * EDIM:  Wg = (const float*)pv; break;
            case EDIM:         bg = (const float*)pv; break;
            default: break;
        }
    }
    if (!x)        x        = (const float*)d_in[0];
    if (!h)        h        = (const float*)d_in[1];
    if (!prev_sel) prev_sel = (const int*)d_in[2];
    if (!Wp)       Wp       = (const float*)d_in[3];
    if (!bp)       bp       = (const float*)d_in[4];
    if (!tau)      tau      = (const float*)d_in[5];
    if (!A)        A        = (const float*)d_in[6];
    if (!Bm)       Bm       = (const float*)d_in[7];
    if (!Wg)       Wg       = (const float*)d_in[8];
    if (!bg)       bg       = (const float*)d_in[9];

    static int attr_done = 0;
    if (!attr_done) {
        cudaFuncSetAttribute(gemm_fused, cudaFuncAttributeMaxDynamicSharedMemorySize, SMEM_GEMM);
        cudaFuncSetAttribute(k_epi, cudaFuncAttributeMaxDynamicSharedMemorySize, SMEM_EPI);
        attr_done = 1;
    }

    float  *Wptr = 0, *Tp = 0;
    __half *Wth = 0;
    cudaGetSymbolAddress((void**)&Wptr, g_W);
    cudaGetSymbolAddress((void**)&Wth, g_Wth);
    cudaGetSymbolAddress((void**)&Tp, g_T);
    float* out = (float*)d_out;

    // 1) weights: fp32 k-major + fp16 n-major transposed; g_c; g_cnt=0
    k_prep<<<KTOT / 16, 256>>>(Wp, Bm, A, bp);
    // 2) T = [h | x] @ W   (single-pass fp16 mma, fp32 accum)
    dim3 grid(BATCH / 128, 2);
    gemm_fused<<<grid, 256, SMEM_GEMM>>>(h, x, Wth, Tp);
    // 3) epilogue + ambiguity flagging
    k_epi<<<BATCH / EROWS, 256, SMEM_EPI>>>(h, prev_sel, tau, Wg, bg, out, BATCH);
    // 4) exact fp32 recompute of flagged rows
    dim3 fgrid(MAXFIX / 64, KSPL);
    k_fixT<<<fgrid, 256>>>(h, x, Wptr);
    k_fixEpi<<<2048, 256>>>(h, prev_sel, tau, Wg, bg, out, BATCH);
}

// round 10
// speedup vs baseline: 3.6686x; 1.1117x over previous
#include <cuda_runtime.h>
#include <cuda_fp16.h>
#include <cstdint>

#define BATCH 65536
#define HID   4096
#define RDIM  256
#define EDIM  64
#define TOPK  2
#define KTOT  (RDIM + HID)        // 4352
#define NS    (KTOT / 32)         // 136 stages
#define THR   1e-3f               // ambiguity threshold on logit gaps
#define MAXFIX 4096               // max rows recomputed exactly
#define KSPL  16                  // K splits in fixup
#define KCHUNK (KTOT / KSPL)      // 272

// ---------------- device scratch ----------------
__device__ float  g_W[(size_t)KTOT * RDIM];    // fp32 [K][256] (fixup)
__device__ __half g_Wth[(size_t)RDIM * KTOT];  // fp16 [N][K] n-major (main GEMM)
__device__ float  g_c[RDIM];                   // bp @ Bm
__device__ float  g_invtau[RDIM];              // 1 / tau
__device__ float  g_T[(size_t)BATCH * RDIM];   // fp16-mma h@A + x@Wf
__device__ int    g_cnt;
__device__ int    g_rows[BATCH];
__device__ float  g_part[(size_t)MAXFIX * KSPL * RDIM];

// ---------------- helpers ----------------
__device__ __forceinline__ uint32_t smem_u32(const void* p) {
    uint32_t a;
    asm("{ .reg .u64 t; cvta.to.shared.u64 t, %1; cvt.u32.u64 %0, t; }"
        : "=r"(a) : "l"(p));
    return a;
}
__device__ __forceinline__ uint32_t pack_h2(float lo, float hi) {
    uint32_t r;
    asm("cvt.rn.f16x2.f32 %0, %1, %2;" : "=r"(r) : "f"(hi), "f"(lo));
    return r;
}
__device__ __forceinline__ void mma_f16(float d[4],
                                        uint32_t a0, uint32_t a1, uint32_t a2, uint32_t a3,
                                        uint32_t b0, uint32_t b1) {
    asm volatile(
        "mma.sync.aligned.m16n8k16.row.col.f32.f16.f16.f32 "
        "{%0,%1,%2,%3}, {%4,%5,%6,%7}, {%8,%9}, {%0,%1,%2,%3};"
        : "+f"(d[0]), "+f"(d[1]), "+f"(d[2]), "+f"(d[3])
        : "r"(a0), "r"(a1), "r"(a2), "r"(a3), "r"(b0), "r"(b1));
}
// fast tanh: 2 MUFU, rel err ~1e-6 (flagged rows are re-done exactly)
__device__ __forceinline__ float fast_tanh(float x) {
    x = fminf(fmaxf(x, -20.f), 20.f);
    float e = __expf(2.f * x);
    return __fdividef(e - 1.f, e + 1.f);
}
#define CP_ASYNC16(dst, src) \
    asm volatile("cp.async.cg.shared.global [%0], [%1], 16;" :: "r"(dst), "l"(src))
#define CP_COMMIT() asm volatile("cp.async.commit_group;" ::: "memory")
#define CP_WAIT1()  asm volatile("cp.async.wait_group 1;" ::: "memory")

// ---------------- GEMM smem layout ----------------
#define A_ST 36
#define B_STH 40
#define ABUF (128 * A_ST * 4)          // 18432 B
#define BBUF (128 * B_STH * 2)         // 10240 B
#define OFF_A(b) ((b) * ABUF)
#define OFF_B(b) (3 * ABUF + (b) * BBUF)
#define SMEM_GEMM (3 * ABUF + 3 * BBUF)   // 86016 B -> 2 CTAs/SM

// ===========================================================================
// Single-pass FP16 GEMM: T[B,256] = [h | x] @ W[4352,256]  (unchanged)
// ===========================================================================
__global__ __launch_bounds__(256, 2)
void gemm_fused(const float* __restrict__ Xh, const float* __restrict__ Xx,
                const __half* __restrict__ Wt, float* __restrict__ C)
{
    extern __shared__ __align__(128) char smem[];
    const uint32_t sb = smem_u32(smem);

    const int tid  = threadIdx.x;
    const int warp = tid >> 5;
    const int lane = tid & 31;
    const int g    = lane >> 2;
    const int tg   = lane & 3;
    const int wm   = (warp >> 2) * 64;
    const int wn   = (warp & 3) * 32;
    const int m0   = blockIdx.x * 128;
    const int n0   = blockIdx.y * 128;

    float d[4][4][4];
#pragma unroll
    for (int mt = 0; mt < 4; mt++)
#pragma unroll
        for (int nt = 0; nt < 4; nt++)
#pragma unroll
            for (int q = 0; q < 4; q++) d[mt][nt][q] = 0.f;

    auto issue = [&](int s) {
        const int k0  = s * 32;
        const int buf = s % 3;
        uint32_t abase = sb + OFF_A(buf);
#pragma unroll
        for (int i = 0; i < 4; i++) {
            int lin = i * 256 + tid;
            int row = lin >> 3;
            int c4  = lin & 7;
            int kg  = k0 + c4 * 4;
            const float* src = (kg < RDIM)
                ? (Xh + (size_t)(m0 + row) * RDIM + kg)
                : (Xx + (size_t)(m0 + row) * HID + (kg - RDIM));
            CP_ASYNC16(abase + (uint32_t)(row * A_ST + c4 * 4) * 4, src);
        }
        uint32_t bbase = sb + OFF_B(buf);
#pragma unroll
        for (int i = 0; i < 2; i++) {
            int lin = i * 256 + tid;
            int nr  = lin >> 2;
            int c8  = lin & 3;
            CP_ASYNC16(bbase + (uint32_t)(nr * B_STH + c8 * 8) * 2,
                       Wt + (size_t)(n0 + nr) * KTOT + k0 + c8 * 8);
        }
        CP_COMMIT();
    };

    auto compute = [&](int buf) {
        const float*  As = (const float*)(smem + OFF_A(buf));
        const __half* Bs = (const __half*)(smem + OFF_B(buf));
#pragma unroll
        for (int k16 = 0; k16 < 2; k16++) {
            const int kk = k16 * 16;
            uint32_t b0[4], b1[4];
#pragma unroll
            for (int nt = 0; nt < 4; nt++) {
                int nb = wn + nt * 8 + g;
                b0[nt] = *reinterpret_cast<const uint32_t*>(&Bs[nb * B_STH + kk + 2 * tg]);
                b1[nt] = *reinterpret_cast<const uint32_t*>(&Bs[nb * B_STH + kk + 2 * tg + 8]);
            }
#pragma unroll
            for (int mt = 0; mt < 4; mt++) {
                int r = (wm + mt * 16 + g) * A_ST + kk + 2 * tg;
                float2 v0 = *reinterpret_cast<const float2*>(&As[r]);
                float2 v1 = *reinterpret_cast<const float2*>(&As[r + 8 * A_ST]);
                float2 v2 = *reinterpret_cast<const float2*>(&As[r + 8]);
                float2 v3 = *reinterpret_cast<const float2*>(&As[r + 8 * A_ST + 8]);
                uint32_t a0 = pack_h2(v0.x, v0.y);
                uint32_t a1 = pack_h2(v1.x, v1.y);
                uint32_t a2 = pack_h2(v2.x, v2.y);
                uint32_t a3 = pack_h2(v3.x, v3.y);
#pragma unroll
                for (int nt = 0; nt < 4; nt++)
                    mma_f16(d[mt][nt], a0, a1, a2, a3, b0[nt], b1[nt]);
            }
        }
    };

    issue(0);
    issue(1);
    for (int s = 0; s < NS; s++) {
        CP_WAIT1();
        __syncthreads();
        if (s + 2 < NS) issue(s + 2); else CP_COMMIT();
        compute(s % 3);
    }

#pragma unroll
    for (int mt = 0; mt < 4; mt++) {
        int r0 = m0 + wm + mt * 16 + g;
#pragma unroll
        for (int nt = 0; nt < 4; nt++) {
            int c0 = n0 + wn + nt * 8 + tg * 2;
            *reinterpret_cast<float2*>(C + (size_t)r0 * 256 + c0) =
                make_float2(d[mt][nt][0], d[mt][nt][1]);
            *reinterpret_cast<float2*>(C + (size_t)(r0 + 8) * 256 + c0) =
                make_float2(d[mt][nt][2], d[mt][nt][3]);
        }
    }
}

// ===========================================================================
// Prep: g_W fp32 + g_Wth fp16 transposed; g_c; g_invtau; g_cnt=0.
// ===========================================================================
__global__ __launch_bounds__(256)
void k_prep(const float* __restrict__ Wp, const float* __restrict__ Bm,
            const float* __restrict__ A, const float* __restrict__ bp,
            const float* __restrict__ tau)
{
    __shared__ float sW16[16][257];
    const int tid = threadIdx.x;
    const int kb = blockIdx.x * 16;
    if (blockIdx.x == 0 && tid == 0) g_cnt = 0;

    float vals[16];
    if (kb < RDIM) {
#pragma unroll
        for (int r = 0; r < 16; r++) {
            vals[r] = A[(size_t)(kb + r) * RDIM + tid];
            g_W[(size_t)(kb + r) * RDIM + tid] = vals[r];
        }
    } else {
        const int i0 = kb - RDIM;
#pragma unroll
        for (int r = 0; r < 16; r++)
            sW16[r][tid] = Wp[(size_t)(i0 + r) * RDIM + tid];
        __syncthreads();
#pragma unroll
        for (int r = 0; r < 16; r++) vals[r] = 0.f;
#pragma unroll 4
        for (int k = 0; k < RDIM; k++) {
            float bmv = Bm[k * RDIM + tid];
#pragma unroll
            for (int r = 0; r < 16; r++)
                vals[r] = fmaf(sW16[r][k], bmv, vals[r]);
        }
#pragma unroll
        for (int r = 0; r < 16; r++)
            g_W[(size_t)(kb + r) * RDIM + tid] = vals[r];
    }

    {
        uint32_t p[8];
#pragma unroll
        for (int j = 0; j < 8; j++) {
            uint32_t r;
            asm("cvt.rn.f16x2.f32 %0, %1, %2;" : "=r"(r)
                : "f"(vals[2 * j + 1]), "f"(vals[2 * j]));
            p[j] = r;
        }
        uint4* dst = reinterpret_cast<uint4*>(
            reinterpret_cast<char*>(g_Wth) + ((size_t)tid * KTOT + kb) * 2);
        dst[0] = make_uint4(p[0], p[1], p[2], p[3]);
        dst[1] = make_uint4(p[4], p[5], p[6], p[7]);
    }

    if (blockIdx.x == 0) {
        float c = 0.f;
#pragma unroll 4
        for (int k = 0; k < RDIM; k++)
            c = fmaf(bp[k], Bm[k * RDIM + tid], c);
        g_c[tid] = c;
        g_invtau[tid] = 1.f / tau[tid];
    }
}

// ===========================================================================
// Epilogue: 32 rows/block; fast tanh + invtau; flags rows w/ gap < THR.
// ===========================================================================
#define EROWS   32
#define WG_ST2  68
#define H_ST    260
#define SMEM_EPI (256 * WG_ST2 * 4 + EROWS * H_ST * 4 + EROWS * 64 * 4)  // 111104
__global__ __launch_bounds__(256)
void k_epi(const float* __restrict__ h, const int* __restrict__ prev_sel,
           const float* __restrict__ Wg, const float* __restrict__ bg,
           float* __restrict__ out, int B)
{
    extern __shared__ __align__(16) char esm[];
    float* sWg = (float*)esm;                               // [256][68] k-major
    float* sH  = (float*)(esm + 256 * WG_ST2 * 4);          // [32][260]
    float* sL  = (float*)(esm + 256 * WG_ST2 * 4 + EROWS * H_ST * 4); // [32][64]
    const int tid = threadIdx.x;
    const size_t r0 = (size_t)blockIdx.x * EROWS;

    // Wg fill
#pragma unroll
    for (int i = 0; i < 16; i++) {
        int f = i * 256 + tid;
        int k = f >> 4;
        int e4 = (f & 15) * 4;
        *reinterpret_cast<float4*>(&sWg[k * WG_ST2 + e4]) =
            *reinterpret_cast<const float4*>(Wg + k * 64 + e4);
    }
    // tanh update, float4 loads: thread -> (row, 4 cols)
#pragma unroll
    for (int it = 0; it < 8; it++) {
        int lin = it * 256 + tid;        // 0..2047
        int row = lin >> 6;              // 0..31
        int c4  = (lin & 63) * 4;        // col base
        size_t gbase = (r0 + row) * 256 + c4;
        float4 hv = *reinterpret_cast<const float4*>(h + gbase);
        float4 tv = *reinterpret_cast<const float4*>(&g_T[gbase]);
        float4 cv = *reinterpret_cast<const float4*>(&g_c[c4]);
        float4 iv = *reinterpret_cast<const float4*>(&g_invtau[c4]);
        float4 r;
        r.x = hv.x + 0.1f * (-hv.x * iv.x + fast_tanh(tv.x + cv.x));
        r.y = hv.y + 0.1f * (-hv.y * iv.y + fast_tanh(tv.y + cv.y));
        r.z = hv.z + 0.1f * (-hv.z * iv.z + fast_tanh(tv.z + cv.z));
        r.w = hv.w + 0.1f * (-hv.w * iv.w + fast_tanh(tv.w + cv.w));
        *reinterpret_cast<float4*>(&sH[row * H_ST + c4]) = r;
    }
    __syncthreads();

    // logits: thread -> 4 experts x 2 rows
    {
        const int eg = (tid & 15) * 4;
        const int rb = tid >> 4;
        float4 acc0 = make_float4(0.f, 0.f, 0.f, 0.f);
        float4 acc1 = make_float4(0.f, 0.f, 0.f, 0.f);
        const float* h0 = sH + rb * H_ST;
        const float* h1 = sH + (rb + 16) * H_ST;
#pragma unroll 8
        for (int k = 0; k < RDIM; k++) {
            float4 w = *reinterpret_cast<const float4*>(&sWg[k * WG_ST2 + eg]);
            float a = h0[k], b = h1[k];
            acc0.x = fmaf(a, w.x, acc0.x); acc0.y = fmaf(a, w.y, acc0.y);
            acc0.z = fmaf(a, w.z, acc0.z); acc0.w = fmaf(a, w.w, acc0.w);
            acc1.x = fmaf(b, w.x, acc1.x); acc1.y = fmaf(b, w.y, acc1.y);
            acc1.z = fmaf(b, w.z, acc1.z); acc1.w = fmaf(b, w.w, acc1.w);
        }
        float4 bgv = *reinterpret_cast<const float4*>(bg + eg);
        acc0.x += bgv.x; acc0.y += bgv.y; acc0.z += bgv.z; acc0.w += bgv.w;
        acc1.x += bgv.x; acc1.y += bgv.y; acc1.z += bgv.z; acc1.w += bgv.w;
        *reinterpret_cast<float4*>(&sL[rb * 64 + eg]) = acc0;
        *reinterpret_cast<float4*>(&sL[(rb + 16) * 64 + eg]) = acc1;
    }
    __syncthreads();

    if (tid < EROWS) {
        int row = tid;
        size_t orow = r0 + row;
        int p0 = prev_sel[orow * 2 + 0];
        int p1 = prev_sel[orow * 2 + 1];
        float v1 = -1e30f, v2 = -1e30f, v3 = -1e30f;
        int i1 = 0, i2 = 0;
#pragma unroll
        for (int q = 0; q < 64; q++) {
            float v = sL[row * 64 + q] + ((q == p0 || q == p1) ? 0.1f : 0.f);
            if (v > v1)      { v3 = v2; v2 = v1; i2 = i1; v1 = v; i1 = q; }
            else if (v > v2) { v3 = v2; v2 = v; i2 = q; }
            else if (v > v3) { v3 = v; }
        }
        float gap = fminf(v1 - v2, v2 - v3);
        if (gap < THR) {
            int slot = atomicAdd(&g_cnt, 1);
            if (slot < BATCH) g_rows[slot] = (int)orow;
        }
        float e2 = expf(v2 - v1);
        float sm = 1.f + e2;
        out[orow * 2 + 0] = (float)i1;
        out[orow * 2 + 1] = (float)i2;
        size_t woff = (size_t)2 * B;
        out[woff + orow * 2 + 0] = 1.f / sm;
        out[woff + orow * 2 + 1] = e2 / sm;
    }
}

// ===========================================================================
// Fixup GEMM, split-K: grid (MAXFIX/64, KSPL), fp32 exact partials.
// ===========================================================================
__global__ __launch_bounds__(256)
void k_fixT(const float* __restrict__ h, const float* __restrict__ x,
            const float* __restrict__ W)
{
    int nrows = g_cnt; if (nrows > MAXFIX) nrows = MAXFIX;
    const int m0 = blockIdx.x * 64;
    if (m0 >= nrows) return;
    const int ks = blockIdx.y;
    const int kbase = ks * KCHUNK;

    __shared__ float sX[64][16];
    __shared__ float sW[16][256];
    __shared__ int   srows[64];

    const int tid = threadIdx.x;
    const int tx = tid & 31, ty = tid >> 5;
    const int xr = tid >> 2, xq = tid & 3;
    const int wr = tid >> 6, wc = tid & 63;

    if (tid < 64) {
        int idx = m0 + tid;
        srows[tid] = g_rows[idx < nrows ? idx : nrows - 1];
    }
    __syncthreads();

    float acc[8][8];
#pragma unroll
    for (int i = 0; i < 8; i++)
#pragma unroll
        for (int j = 0; j < 8; j++) acc[i][j] = 0.f;

    for (int k0 = kbase; k0 < kbase + KCHUNK; k0 += 16) {
        {
            int row = srows[xr];
            int kg = k0 + xq * 4;
            const float* src = (kg < RDIM)
                ? (h + (size_t)row * RDIM + kg)
                : (x + (size_t)row * HID + (kg - RDIM));
            *reinterpret_cast<float4*>(&sX[xr][xq * 4]) =
                *reinterpret_cast<const float4*>(src);
        }
#pragma unroll
        for (int r = 0; r < 4; r++)
            *reinterpret_cast<float4*>(&sW[wr + 4 * r][wc * 4]) =
                *reinterpret_cast<const float4*>(W + (size_t)(k0 + wr + 4 * r) * 256 + wc * 4);
        __syncthreads();

#pragma unroll
        for (int k = 0; k < 16; k++) {
            float a[8], b[8];
#pragma unroll
            for (int i = 0; i < 8; i++) a[i] = sX[ty + 8 * i][k];
#pragma unroll
            for (int j = 0; j < 8; j++) b[j] = sW[k][tx + 32 * j];
#pragma unroll
            for (int i = 0; i < 8; i++)
#pragma unroll
                for (int j = 0; j < 8; j++)
                    acc[i][j] = fmaf(a[i], b[j], acc[i][j]);
        }
        __syncthreads();
    }

#pragma unroll
    for (int i = 0; i < 8; i++) {
        int rl = ty + 8 * i;
        if (m0 + rl < nrows) {
            float* dst = &g_part[((size_t)(m0 + rl) * KSPL + ks) * RDIM];
#pragma unroll
            for (int j = 0; j < 8; j++)
                dst[tx + 32 * j] = acc[i][j];
        }
    }
}

// ===========================================================================
// Fixup epilogue: reduce K-split partials, exact recompute, overwrite.
// ===========================================================================
__global__ __launch_bounds__(256)
void k_fixEpi(const float* __restrict__ h, const int* __restrict__ prev_sel,
              const float* __restrict__ tau, const float* __restrict__ Wg,
              const float* __restrict__ bg, float* __restrict__ out, int B)
{
    __shared__ float sH[RDIM];
    __shared__ float sPart[4][EDIM];
    __shared__ float sL[EDIM];
    const int j = threadIdx.x;
    int n = g_cnt; if (n > MAXFIX) n = MAXFIX;

    for (int r = blockIdx.x; r < n; r += gridDim.x) {
        size_t row = (size_t)g_rows[r];
        float Tj = 0.f;
#pragma unroll
        for (int ks = 0; ks < KSPL; ks++)
            Tj += g_part[((size_t)r * KSPL + ks) * RDIM + j];
        float hj = h[row * 256 + j];
        sH[j] = hj + 0.1f * (-hj / tau[j] + tanhf(Tj + g_c[j]));
        __syncthreads();

        int e = j & 63, p = j >> 6;
        float acc = 0.f;
#pragma unroll 8
        for (int k = p * 64; k < p * 64 + 64; k++)
            acc = fmaf(sH[k], Wg[k * EDIM + e], acc);
        sPart[p][e] = acc;
        __syncthreads();

        if (j < EDIM) {
            float lg = sPart[0][j] + sPart[1][j] + sPart[2][j] + sPart[3][j] + bg[j];
            int p0 = prev_sel[row * 2 + 0];
            int p1 = prev_sel[row * 2 + 1];
            if (j == p0 || j == p1) lg += 0.1f;
            sL[j] = lg;
        }
        __syncthreads();

        if (j == 0) {
            float v1 = -1e30f, v2 = -1e30f;
            int i1 = 0, i2 = 0;
#pragma unroll
            for (int q = 0; q < 64; q++) {
                float v = sL[q];
                if (v > v1) { v2 = v1; i2 = i1; v1 = v; i1 = q; }
                else if (v > v2) { v2 = v; i2 = q; }
            }
            float e2 = expf(v2 - v1);
            float sm = 1.f + e2;
            out[row * 2 + 0] = (float)i1;
            out[row * 2 + 1] = (float)i2;
            size_t woff = (size_t)2 * B;
            out[woff + row * 2 + 0] = 1.f / sm;
            out[woff + row * 2 + 1] = e2 / sm;
        }
        __syncthreads();
    }
}

// ===========================================================================
extern "C" void kernel_launch(void* const* d_in, const int* in_sizes, int n_in,
                              void* d_out, int out_size)
{
    const float *x = 0, *h = 0, *Wp = 0, *bp = 0, *tau = 0, *A = 0, *Bm = 0,
                *Wg = 0, *bg = 0;
    const int* prev_sel = 0;
    for (int i = 0; i < n_in; i++) {
        int s = in_sizes[i];
        const void* pv = d_in[i];
        switch (s) {
            case BATCH * HID:  x = (const float*)pv; break;
            case BATCH * RDIM: h = (const float*)pv; break;
            case BATCH * TOPK: prev_sel = (const int*)pv; break;
            case HID * RDIM:   Wp = (const float*)pv; break;
            case RDIM:         if (!bp) bp = (const float*)pv; else tau = (const float*)pv; break;
            case RDIM * RDIM:  if (!A) A = (const float*)pv; else Bm = (const float*)pv; break;
            case RDIM * EDIM:  Wg = (const float*)pv; break;
            case EDIM:         bg = (const float*)pv; break;
            default: break;
        }
    }
    if (!x)        x        = (const float*)d_in[0];
    if (!h)        h        = (const float*)d_in[1];
    if (!prev_sel) prev_sel = (const int*)d_in[2];
    if (!Wp)       Wp       = (const float*)d_in[3];
    if (!bp)       bp       = (const float*)d_in[4];
    if (!tau)      tau      = (const float*)d_in[5];
    if (!A)        A        = (const float*)d_in[6];
    if (!Bm)       Bm       = (const float*)d_in[7];
    if (!Wg)       Wg       = (const float*)d_in[8];
    if (!bg)       bg       = (const float*)d_in[9];

    static int attr_done = 0;
    if (!attr_done) {
        cudaFuncSetAttribute(gemm_fused, cudaFuncAttributeMaxDynamicSharedMemorySize, SMEM_GEMM);
        cudaFuncSetAttribute(k_epi, cudaFuncAttributeMaxDynamicSharedMemorySize, SMEM_EPI);
        attr_done = 1;
    }

    float  *Wptr = 0, *Tp = 0;
    __half *Wth = 0;
    cudaGetSymbolAddress((void**)&Wptr, g_W);
    cudaGetSymbolAddress((void**)&Wth, g_Wth);
    cudaGetSymbolAddress((void**)&Tp, g_T);
    float* out = (float*)d_out;

    // 1) weights + invtau + counters
    k_prep<<<KTOT / 16, 256>>>(Wp, Bm, A, bp, tau);
    // 2) T = [h | x] @ W   (single-pass fp16 mma, fp32 accum)
    dim3 grid(BATCH / 128, 2);
    gemm_fused<<<grid, 256, SMEM_GEMM>>>(h, x, Wth, Tp);
    // 3) epilogue + ambiguity flagging
    k_epi<<<BATCH / EROWS, 256, SMEM_EPI>>>(h, prev_sel, Wg, bg, out, BATCH);
    // 4) exact fp32 recompute of flagged rows
    dim3 fgrid(MAXFIX / 64, KSPL);
    k_fixT<<<fgrid, 256>>>(h, x, Wptr);
    k_fixEpi<<<2048, 256>>>(h, prev_sel, tau, Wg, bg, out, BATCH);
}

// round 11
// speedup vs baseline: 3.6710x; 1.0006x over previous
#include <cuda_runtime.h>
#include <cuda_fp16.h>
#include <cstdint>

#define BATCH 65536
#define HID   4096
#define RDIM  256
#define EDIM  64
#define TOPK  2
#define KTOT  (RDIM + HID)        // 4352
#define NS    (KTOT / 32)         // 136 stages
#define THR   1e-3f
#define MAXFIX 4096
#define KSPL  16
#define KCHUNK (KTOT / KSPL)      // 272
#define NMBLK (BATCH / 128)       // 512 row blocks

// ---------------- device scratch ----------------
__device__ float  g_W[(size_t)KTOT * RDIM];    // fp32 [K][256] (fixup)
__device__ __half g_Wth[(size_t)RDIM * KTOT];  // fp16 [N][K] n-major (main GEMM)
__device__ float  g_c[RDIM];
__device__ float  g_invtau[RDIM];
__device__ float  g_T[(size_t)BATCH * RDIM];
__device__ int    g_cnt;
__device__ int    g_rows[BATCH];
__device__ int    g_flag[NMBLK];               // per row-block arrival counter
__device__ float  g_part[(size_t)MAXFIX * KSPL * RDIM];

// ---------------- helpers ----------------
__device__ __forceinline__ uint32_t smem_u32(const void* p) {
    uint32_t a;
    asm("{ .reg .u64 t; cvta.to.shared.u64 t, %1; cvt.u32.u64 %0, t; }"
        : "=r"(a) : "l"(p));
    return a;
}
__device__ __forceinline__ uint32_t pack_h2(float lo, float hi) {
    uint32_t r;
    asm("cvt.rn.f16x2.f32 %0, %1, %2;" : "=r"(r) : "f"(hi), "f"(lo));
    return r;
}
__device__ __forceinline__ void mma_f16(float d[4],
                                        uint32_t a0, uint32_t a1, uint32_t a2, uint32_t a3,
                                        uint32_t b0, uint32_t b1) {
    asm volatile(
        "mma.sync.aligned.m16n8k16.row.col.f32.f16.f16.f32 "
        "{%0,%1,%2,%3}, {%4,%5,%6,%7}, {%8,%9}, {%0,%1,%2,%3};"
        : "+f"(d[0]), "+f"(d[1]), "+f"(d[2]), "+f"(d[3])
        : "r"(a0), "r"(a1), "r"(a2), "r"(a3), "r"(b0), "r"(b1));
}
__device__ __forceinline__ float fast_tanh(float x) {
    x = fminf(fmaxf(x, -20.f), 20.f);
    float e = __expf(2.f * x);
    return __fdividef(e - 1.f, e + 1.f);
}
#define CP_ASYNC16(dst, src) \
    asm volatile("cp.async.cg.shared.global [%0], [%1], 16;" :: "r"(dst), "l"(src))
#define CP_COMMIT() asm volatile("cp.async.commit_group;" ::: "memory")
#define CP_WAIT1()  asm volatile("cp.async.wait_group 1;" ::: "memory")

// ---------------- GEMM smem layout ----------------
#define A_ST 36
#define B_STH 40
#define ABUF (128 * A_ST * 4)          // 18432 B
#define BBUF (128 * B_STH * 2)         // 10240 B
#define OFF_A(b) ((b) * ABUF)
#define OFF_B(b) (3 * ABUF + (b) * BBUF)
#define SMEM_GEMM (3 * ABUF + 3 * BBUF)   // 86016 B -> 2 CTAs/SM
// epilogue smem reuse (fits in 86016)
#define H_ST 260

// ===========================================================================
// FP16 GEMM + fused epilogue. T[B,256] = [h|x] @ W; second-arriving CTA of
// each 128-row block runs the tanh/logits/top-2 epilogue for that block,
// overlapped with the remaining CTAs' MMA work.
// ===========================================================================
__global__ __launch_bounds__(256, 2)
void gemm_fused(const float* __restrict__ Xh, const float* __restrict__ Xx,
                const __half* __restrict__ Wt, float* __restrict__ C,
                const int* __restrict__ prev_sel, const float* __restrict__ Wg,
                const float* __restrict__ bg, float* __restrict__ out, int B)
{
    extern __shared__ __align__(128) char smem[];
    const uint32_t sb = smem_u32(smem);

    const int tid  = threadIdx.x;
    const int warp = tid >> 5;
    const int lane = tid & 31;
    const int g    = lane >> 2;
    const int tg   = lane & 3;
    const int wm   = (warp >> 2) * 64;
    const int wn   = (warp & 3) * 32;
    const int m0   = blockIdx.x * 128;
    const int n0   = blockIdx.y * 128;

    float d[4][4][4];
#pragma unroll
    for (int mt = 0; mt < 4; mt++)
#pragma unroll
        for (int nt = 0; nt < 4; nt++)
#pragma unroll
            for (int q = 0; q < 4; q++) d[mt][nt][q] = 0.f;

    auto issue = [&](int s) {
        const int k0  = s * 32;
        const int buf = s % 3;
        uint32_t abase = sb + OFF_A(buf);
#pragma unroll
        for (int i = 0; i < 4; i++) {
            int lin = i * 256 + tid;
            int row = lin >> 3;
            int c4  = lin & 7;
            int kg  = k0 + c4 * 4;
            const float* src = (kg < RDIM)
                ? (Xh + (size_t)(m0 + row) * RDIM + kg)
                : (Xx + (size_t)(m0 + row) * HID + (kg - RDIM));
            CP_ASYNC16(abase + (uint32_t)(row * A_ST + c4 * 4) * 4, src);
        }
        uint32_t bbase = sb + OFF_B(buf);
#pragma unroll
        for (int i = 0; i < 2; i++) {
            int lin = i * 256 + tid;
            int nr  = lin >> 2;
            int c8  = lin & 3;
            CP_ASYNC16(bbase + (uint32_t)(nr * B_STH + c8 * 8) * 2,
                       Wt + (size_t)(n0 + nr) * KTOT + k0 + c8 * 8);
        }
        CP_COMMIT();
    };

    auto compute = [&](int buf) {
        const float*  As = (const float*)(smem + OFF_A(buf));
        const __half* Bs = (const __half*)(smem + OFF_B(buf));
#pragma unroll
        for (int k16 = 0; k16 < 2; k16++) {
            const int kk = k16 * 16;
            uint32_t b0[4], b1[4];
#pragma unroll
            for (int nt = 0; nt < 4; nt++) {
                int nb = wn + nt * 8 + g;
                b0[nt] = *reinterpret_cast<const uint32_t*>(&Bs[nb * B_STH + kk + 2 * tg]);
                b1[nt] = *reinterpret_cast<const uint32_t*>(&Bs[nb * B_STH + kk + 2 * tg + 8]);
            }
#pragma unroll
            for (int mt = 0; mt < 4; mt++) {
                int r = (wm + mt * 16 + g) * A_ST + kk + 2 * tg;
                float2 v0 = *reinterpret_cast<const float2*>(&As[r]);
                float2 v1 = *reinterpret_cast<const float2*>(&As[r + 8 * A_ST]);
                float2 v2 = *reinterpret_cast<const float2*>(&As[r + 8]);
                float2 v3 = *reinterpret_cast<const float2*>(&As[r + 8 * A_ST + 8]);
                uint32_t a0 = pack_h2(v0.x, v0.y);
                uint32_t a1 = pack_h2(v1.x, v1.y);
                uint32_t a2 = pack_h2(v2.x, v2.y);
                uint32_t a3 = pack_h2(v3.x, v3.y);
#pragma unroll
                for (int nt = 0; nt < 4; nt++)
                    mma_f16(d[mt][nt], a0, a1, a2, a3, b0[nt], b1[nt]);
            }
        }
    };

    issue(0);
    issue(1);
    for (int s = 0; s < NS; s++) {
        CP_WAIT1();
        __syncthreads();
        if (s + 2 < NS) issue(s + 2); else CP_COMMIT();
        compute(s % 3);
    }

    // ---- writeback T ----
#pragma unroll
    for (int mt = 0; mt < 4; mt++) {
        int r0 = m0 + wm + mt * 16 + g;
#pragma unroll
        for (int nt = 0; nt < 4; nt++) {
            int c0 = n0 + wn + nt * 8 + tg * 2;
            *reinterpret_cast<float2*>(C + (size_t)r0 * 256 + c0) =
                make_float2(d[mt][nt][0], d[mt][nt][1]);
            *reinterpret_cast<float2*>(C + (size_t)(r0 + 8) * 256 + c0) =
                make_float2(d[mt][nt][2], d[mt][nt][3]);
        }
    }

    // ---- arrival: second CTA of this row block runs the epilogue ----
    __threadfence();
    __shared__ int s_old;
    __syncthreads();                 // writeback + smem idle before reuse
    if (tid == 0) s_old = atomicAdd(&g_flag[blockIdx.x], 1);
    __syncthreads();
    if (s_old == 0) return;          // first arriver exits
    __threadfence();                 // acquire: other CTA's T writes visible

    float* sH = (float*)smem;                    // [32][260] = 33280 B
    float* sL = (float*)(smem + 33280);          // [32][64]  =  8192 B

#pragma unroll 1
    for (int chunk = 0; chunk < 4; chunk++) {
        const size_t r0 = (size_t)m0 + chunk * 32;
        __syncthreads();
        // tanh update: 8 float4 per thread
#pragma unroll
        for (int it = 0; it < 8; it++) {
            int lin = it * 256 + tid;
            int row = lin >> 6;
            int c4  = (lin & 63) * 4;
            size_t gbase = (r0 + row) * 256 + c4;
            float4 hv = *reinterpret_cast<const float4*>(Xh + gbase);
            float4 tv = *reinterpret_cast<const float4*>(&g_T[gbase]);
            float4 cv = *reinterpret_cast<const float4*>(&g_c[c4]);
            float4 iv = *reinterpret_cast<const float4*>(&g_invtau[c4]);
            float4 r;
            r.x = hv.x + 0.1f * (-hv.x * iv.x + fast_tanh(tv.x + cv.x));
            r.y = hv.y + 0.1f * (-hv.y * iv.y + fast_tanh(tv.y + cv.y));
            r.z = hv.z + 0.1f * (-hv.z * iv.z + fast_tanh(tv.z + cv.z));
            r.w = hv.w + 0.1f * (-hv.w * iv.w + fast_tanh(tv.w + cv.w));
            *reinterpret_cast<float4*>(&sH[row * H_ST + c4]) = r;
        }
        __syncthreads();
        // logits GEMV: thread -> 4 experts x 2 rows; Wg via L1/L2
        {
            const int eg = (tid & 15) * 4;
            const int rb = tid >> 4;
            float4 acc0 = make_float4(0.f, 0.f, 0.f, 0.f);
            float4 acc1 = make_float4(0.f, 0.f, 0.f, 0.f);
            const float* h0 = sH + rb * H_ST;
            const float* h1 = sH + (rb + 16) * H_ST;
#pragma unroll 8
            for (int k = 0; k < RDIM; k++) {
                float4 w = __ldg(reinterpret_cast<const float4*>(Wg + k * 64 + eg));
                float a = h0[k], b = h1[k];
                acc0.x = fmaf(a, w.x, acc0.x); acc0.y = fmaf(a, w.y, acc0.y);
                acc0.z = fmaf(a, w.z, acc0.z); acc0.w = fmaf(a, w.w, acc0.w);
                acc1.x = fmaf(b, w.x, acc1.x); acc1.y = fmaf(b, w.y, acc1.y);
                acc1.z = fmaf(b, w.z, acc1.z); acc1.w = fmaf(b, w.w, acc1.w);
            }
            float4 bgv = *reinterpret_cast<const float4*>(bg + eg);
            acc0.x += bgv.x; acc0.y += bgv.y; acc0.z += bgv.z; acc0.w += bgv.w;
            acc1.x += bgv.x; acc1.y += bgv.y; acc1.z += bgv.z; acc1.w += bgv.w;
            *reinterpret_cast<float4*>(&sL[rb * 64 + eg]) = acc0;
            *reinterpret_cast<float4*>(&sL[(rb + 16) * 64 + eg]) = acc1;
        }
        __syncthreads();
        // top-2 + flag + write
        if (tid < 32) {
            int row = tid;
            size_t orow = r0 + row;
            int p0 = prev_sel[orow * 2 + 0];
            int p1 = prev_sel[orow * 2 + 1];
            float v1 = -1e30f, v2 = -1e30f, v3 = -1e30f;
            int i1 = 0, i2 = 0;
#pragma unroll
            for (int q = 0; q < 64; q++) {
                float v = sL[row * 64 + q] + ((q == p0 || q == p1) ? 0.1f : 0.f);
                if (v > v1)      { v3 = v2; v2 = v1; i2 = i1; v1 = v; i1 = q; }
                else if (v > v2) { v3 = v2; v2 = v; i2 = q; }
                else if (v > v3) { v3 = v; }
            }
            float gap = fminf(v1 - v2, v2 - v3);
            if (gap < THR) {
                int slot = atomicAdd(&g_cnt, 1);
                if (slot < BATCH) g_rows[slot] = (int)orow;
            }
            float e2 = expf(v2 - v1);
            float sm = 1.f + e2;
            out[orow * 2 + 0] = (float)i1;
            out[orow * 2 + 1] = (float)i2;
            size_t woff = (size_t)2 * B;
            out[woff + orow * 2 + 0] = 1.f / sm;
            out[woff + orow * 2 + 1] = e2 / sm;
        }
    }
}

// ===========================================================================
// Prep: g_W fp32 + g_Wth fp16 transposed; g_c; g_invtau; zero g_cnt/g_flag.
// ===========================================================================
__global__ __launch_bounds__(256)
void k_prep(const float* __restrict__ Wp, const float* __restrict__ Bm,
            const float* __restrict__ A, const float* __restrict__ bp,
            const float* __restrict__ tau)
{
    __shared__ float sW16[16][257];
    const int tid = threadIdx.x;
    const int kb = blockIdx.x * 16;
    if (blockIdx.x == 0 && tid == 0) g_cnt = 0;
    if (blockIdx.x < NMBLK / 256) g_flag[blockIdx.x * 256 + tid] = 0;

    float vals[16];
    if (kb < RDIM) {
#pragma unroll
        for (int r = 0; r < 16; r++) {
            vals[r] = A[(size_t)(kb + r) * RDIM + tid];
            g_W[(size_t)(kb + r) * RDIM + tid] = vals[r];
        }
    } else {
        const int i0 = kb - RDIM;
#pragma unroll
        for (int r = 0; r < 16; r++)
            sW16[r][tid] = Wp[(size_t)(i0 + r) * RDIM + tid];
        __syncthreads();
#pragma unroll
        for (int r = 0; r < 16; r++) vals[r] = 0.f;
#pragma unroll 4
        for (int k = 0; k < RDIM; k++) {
            float bmv = Bm[k * RDIM + tid];
#pragma unroll
            for (int r = 0; r < 16; r++)
                vals[r] = fmaf(sW16[r][k], bmv, vals[r]);
        }
#pragma unroll
        for (int r = 0; r < 16; r++)
            g_W[(size_t)(kb + r) * RDIM + tid] = vals[r];
    }

    {
        uint32_t p[8];
#pragma unroll
        for (int j = 0; j < 8; j++) {
            uint32_t r;
            asm("cvt.rn.f16x2.f32 %0, %1, %2;" : "=r"(r)
                : "f"(vals[2 * j + 1]), "f"(vals[2 * j]));
            p[j] = r;
        }
        uint4* dst = reinterpret_cast<uint4*>(
            reinterpret_cast<char*>(g_Wth) + ((size_t)tid * KTOT + kb) * 2);
        dst[0] = make_uint4(p[0], p[1], p[2], p[3]);
        dst[1] = make_uint4(p[4], p[5], p[6], p[7]);
    }

    if (blockIdx.x == 0) {
        float c = 0.f;
#pragma unroll 4
        for (int k = 0; k < RDIM; k++)
            c = fmaf(bp[k], Bm[k * RDIM + tid], c);
        g_c[tid] = c;
        g_invtau[tid] = 1.f / tau[tid];
    }
}

// ===========================================================================
// Fixup GEMM, split-K: exact fp32 partials for flagged rows.
// ===========================================================================
__global__ __launch_bounds__(256)
void k_fixT(const float* __restrict__ h, const float* __restrict__ x,
            const float* __restrict__ W)
{
    int nrows = g_cnt; if (nrows > MAXFIX) nrows = MAXFIX;
    const int m0 = blockIdx.x * 64;
    if (m0 >= nrows) return;
    const int ks = blockIdx.y;
    const int kbase = ks * KCHUNK;

    __shared__ float sX[64][16];
    __shared__ float sW[16][256];
    __shared__ int   srows[64];

    const int tid = threadIdx.x;
    const int tx = tid & 31, ty = tid >> 5;
    const int xr = tid >> 2, xq = tid & 3;
    const int wr = tid >> 6, wc = tid & 63;

    if (tid < 64) {
        int idx = m0 + tid;
        srows[tid] = g_rows[idx < nrows ? idx : nrows - 1];
    }
    __syncthreads();

    float acc[8][8];
#pragma unroll
    for (int i = 0; i < 8; i++)
#pragma unroll
        for (int j = 0; j < 8; j++) acc[i][j] = 0.f;

    for (int k0 = kbase; k0 < kbase + KCHUNK; k0 += 16) {
        {
            int row = srows[xr];
            int kg = k0 + xq * 4;
            const float* src = (kg < RDIM)
                ? (h + (size_t)row * RDIM + kg)
                : (x + (size_t)row * HID + (kg - RDIM));
            *reinterpret_cast<float4*>(&sX[xr][xq * 4]) =
                *reinterpret_cast<const float4*>(src);
        }
#pragma unroll
        for (int r = 0; r < 4; r++)
            *reinterpret_cast<float4*>(&sW[wr + 4 * r][wc * 4]) =
                *reinterpret_cast<const float4*>(W + (size_t)(k0 + wr + 4 * r) * 256 + wc * 4);
        __syncthreads();

#pragma unroll
        for (int k = 0; k < 16; k++) {
            float a[8], b[8];
#pragma unroll
            for (int i = 0; i < 8; i++) a[i] = sX[ty + 8 * i][k];
#pragma unroll
            for (int j = 0; j < 8; j++) b[j] = sW[k][tx + 32 * j];
#pragma unroll
            for (int i = 0; i < 8; i++)
#pragma unroll
                for (int j = 0; j < 8; j++)
                    acc[i][j] = fmaf(a[i], b[j], acc[i][j]);
        }
        __syncthreads();
    }

#pragma unroll
    for (int i = 0; i < 8; i++) {
        int rl = ty + 8 * i;
        if (m0 + rl < nrows) {
            float* dst = &g_part[((size_t)(m0 + rl) * KSPL + ks) * RDIM];
#pragma unroll
            for (int j = 0; j < 8; j++)
                dst[tx + 32 * j] = acc[i][j];
        }
    }
}

// ===========================================================================
// Fixup epilogue: reduce K-split partials, exact recompute, overwrite.
// ===========================================================================
__global__ __launch_bounds__(256)
void k_fixEpi(const float* __restrict__ h, const int* __restrict__ prev_sel,
              const float* __restrict__ tau, const float* __restrict__ Wg,
              const float* __restrict__ bg, float* __restrict__ out, int B)
{
    __shared__ float sH[RDIM];
    __shared__ float sPart[4][EDIM];
    __shared__ float sL[EDIM];
    const int j = threadIdx.x;
    int n = g_cnt; if (n > MAXFIX) n = MAXFIX;

    for (int r = blockIdx.x; r < n; r += gridDim.x) {
        size_t row = (size_t)g_rows[r];
        float Tj = 0.f;
#pragma unroll
        for (int ks = 0; ks < KSPL; ks++)
            Tj += g_part[((size_t)r * KSPL + ks) * RDIM + j];
        float hj = h[row * 256 + j];
        sH[j] = hj + 0.1f * (-hj / tau[j] + tanhf(Tj + g_c[j]));
        __syncthreads();

        int e = j & 63, p = j >> 6;
        float acc = 0.f;
#pragma unroll 8
        for (int k = p * 64; k < p * 64 + 64; k++)
            acc = fmaf(sH[k], Wg[k * EDIM + e], acc);
        sPart[p][e] = acc;
        __syncthreads();

        if (j < EDIM) {
            float lg = sPart[0][j] + sPart[1][j] + sPart[2][j] + sPart[3][j] + bg[j];
            int p0 = prev_sel[row * 2 + 0];
            int p1 = prev_sel[row * 2 + 1];
            if (j == p0 || j == p1) lg += 0.1f;
            sL[j] = lg;
        }
        __syncthreads();

        if (j == 0) {
            float v1 = -1e30f, v2 = -1e30f;
            int i1 = 0, i2 = 0;
#pragma unroll
            for (int q = 0; q < 64; q++) {
                float v = sL[q];
                if (v > v1) { v2 = v1; i2 = i1; v1 = v; i1 = q; }
                else if (v > v2) { v2 = v; i2 = q; }
            }
            float e2 = expf(v2 - v1);
            float sm = 1.f + e2;
            out[row * 2 + 0] = (float)i1;
            out[row * 2 + 1] = (float)i2;
            size_t woff = (size_t)2 * B;
            out[woff + row * 2 + 0] = 1.f / sm;
            out[woff + row * 2 + 1] = e2 / sm;
        }
        __syncthreads();
    }
}

// ===========================================================================
extern "C" void kernel_launch(void* const* d_in, const int* in_sizes, int n_in,
                              void* d_out, int out_size)
{
    const float *x = 0, *h = 0, *Wp = 0, *bp = 0, *tau = 0, *A = 0, *Bm = 0,
                *Wg = 0, *bg = 0;
    const int* prev_sel = 0;
    for (int i = 0; i < n_in; i++) {
        int s = in_sizes[i];
        const void* pv = d_in[i];
        switch (s) {
            case BATCH * HID:  x = (const float*)pv; break;
            case BATCH * RDIM: h = (const float*)pv; break;
            case BATCH * TOPK: prev_sel = (const int*)pv; break;
            case HID * RDIM:   Wp = (const float*)pv; break;
            case RDIM:         if (!bp) bp = (const float*)pv; else tau = (const float*)pv; break;
            case RDIM * RDIM:  if (!A) A = (const float*)pv; else Bm = (const float*)pv; break;
            case RDIM * EDIM:  Wg = (const float*)pv; break;
            case EDIM:         bg = (const float*)pv; break;
            default: break;
        }
    }
    if (!x)        x        = (const float*)d_in[0];
    if (!h)        h        = (const float*)d_in[1];
    if (!prev_sel) prev_sel = (const int*)d_in[2];
    if (!Wp)       Wp       = (const float*)d_in[3];
    if (!bp)       bp       = (const float*)d_in[4];
    if (!tau)      tau      = (const float*)d_in[5];
    if (!A)        A        = (const float*)d_in[6];
    if (!Bm)       Bm       = (const float*)d_in[7];
    if (!Wg)       Wg       = (const float*)d_in[8];
    if (!bg)       bg       = (const float*)d_in[9];

    static int attr_done = 0;
    if (!attr_done) {
        cudaFuncSetAttribute(gemm_fused, cudaFuncAttributeMaxDynamicSharedMemorySize, SMEM_GEMM);
        attr_done = 1;
    }

    float  *Wptr = 0, *Tp = 0;
    __half *Wth = 0;
    cudaGetSymbolAddress((void**)&Wptr, g_W);
    cudaGetSymbolAddress((void**)&Wth, g_Wth);
    cudaGetSymbolAddress((void**)&Tp, g_T);
    float* out = (float*)d_out;

    // 1) weights + invtau + counters/flags
    k_prep<<<KTOT / 16, 256>>>(Wp, Bm, A, bp, tau);
    // 2) GEMM + fused epilogue (second CTA per row block)
    dim3 grid(BATCH / 128, 2);
    gemm_fused<<<grid, 256, SMEM_GEMM>>>(h, x, Wth, Tp, prev_sel, Wg, bg, out, BATCH);
    // 3) exact fp32 recompute of flagged rows
    dim3 fgrid(MAXFIX / 64, KSPL);
    k_fixT<<<fgrid, 256>>>(h, x, Wptr);
    k_fixEpi<<<2048, 256>>>(h, prev_sel, tau, Wg, bg, out, BATCH);
}